// round 12
// baseline (speedup 1.0000x reference)
#include <cuda_runtime.h>
#include <cuda_fp16.h>
#include <cstdint>
#include <cstddef>

// Problem constants
#define T_SEQ  2048
#define NHEAD  16
#define HDIM   1024
#define HD     64
#define BATCH  2
#define MROWS  (BATCH * T_SEQ)   // 4096

// Scratch (device globals; no allocations allowed)
__device__ __half g_qkvh[MROWS * 3 * HDIM];           // qkv fp16
__device__ __half g_hh[MROWS * HDIM];                 // hidden fp16
__device__ __half g_Qh[BATCH * NHEAD * T_SEQ * HD];   // [bh][t][d], fp16, pre-scaled
__device__ __half g_Kh[BATCH * NHEAD * T_SEQ * HD];   // [bh][t][d], fp16
__device__ __half g_Vh[BATCH * NHEAD * T_SEQ * HD];   // [bh][t][d], fp16
__device__ __half g_attn[MROWS * HDIM];               // attention output fp16
__device__ __half g_Bt1[3 * HDIM * HDIM];             // w_qkv^T fp16 [3072,1024]
__device__ __half g_Bt2[HDIM * HDIM];                 // w_out^T fp16 [1024,1024]

// ---------------------------------------------------------------------------
// Helpers
// ---------------------------------------------------------------------------
__device__ __forceinline__ uint32_t packh2(float lo, float hi) {
    uint32_t r;
    asm("cvt.rn.f16x2.f32 %0, %1, %2;" : "=r"(r) : "f"(hi), "f"(lo));
    return r;
}

__device__ __forceinline__ void cp16(uint32_t dst, const void* src) {
    asm volatile("cp.async.cg.shared.global [%0], [%1], 16;\n" :: "r"(dst), "l"(src));
}
__device__ __forceinline__ void cp_commit() {
    asm volatile("cp.async.commit_group;\n");
}
__device__ __forceinline__ void cp_wait3() {
    asm volatile("cp.async.wait_group 3;\n");
}
__device__ __forceinline__ void cp_wait0() {
    asm volatile("cp.async.wait_group 0;\n");
}

__device__ __forceinline__ void mma_f16(float* c, const uint32_t* a, const uint32_t* b) {
    asm volatile(
        "mma.sync.aligned.m16n8k16.row.col.f32.f16.f16.f32 "
        "{%0,%1,%2,%3}, {%4,%5,%6,%7}, {%8,%9}, {%0,%1,%2,%3};"
        : "+f"(c[0]), "+f"(c[1]), "+f"(c[2]), "+f"(c[3])
        : "r"(a[0]), "r"(a[1]), "r"(a[2]), "r"(a[3]), "r"(b[0]), "r"(b[1]));
}

__device__ __forceinline__ void ldsm4(uint32_t* r, uint32_t addr) {
    asm volatile("ldmatrix.sync.aligned.m8n8.x4.shared.b16 {%0,%1,%2,%3}, [%4];"
        : "=r"(r[0]), "=r"(r[1]), "=r"(r[2]), "=r"(r[3]) : "r"(addr));
}

__device__ __forceinline__ void ldsm4t(uint32_t* r, uint32_t addr) {
    asm volatile("ldmatrix.sync.aligned.m8n8.x4.trans.shared.b16 {%0,%1,%2,%3}, [%4];"
        : "=r"(r[0]), "=r"(r[1]), "=r"(r[2]), "=r"(r[3]) : "r"(addr));
}

// ---------------------------------------------------------------------------
// fp16 mma.sync GEMM — 5-stage, ONE barrier per chunk, prefetch distance 4.
// C[M,N] = Ah[M,K] @ Bth[N,K]^T (+bias), fp32 accumulate.
// 128x128x32 CTA chunk, 256 threads, 8 warps (2x4), warp tile 64x32.
// HOUT: write __half output, else float.
// ---------------------------------------------------------------------------
#define HSTR 40                            // halves per smem row (32 + 8 pad), 80B
#define HSTAGE_BYTES (2 * 128 * HSTR * 2)  // A tile then B tile = 20480
#define NSTG 5
#define HGEMM_SMEM (NSTG * HSTAGE_BYTES)   // 102400

template<bool HOUT>
__global__ __launch_bounds__(256) void h16_mma_gemm(
    const __half* __restrict__ A, const __half* __restrict__ Bt,
    const float* __restrict__ bias, void* __restrict__ Cv,
    int N, int K)
{
    extern __shared__ __align__(128) char smc[];
    const uint32_t sbase = (uint32_t)__cvta_generic_to_shared(smc);

    const int tid = threadIdx.x, lane = tid & 31, w = tid >> 5;
    const int wm = w & 1, wn = w >> 1;           // warp 2x4 grid
    const int g = lane >> 2, tig = lane & 3;
    const int bm = blockIdx.y * 128, bn = blockIdx.x * 128;

    const int r0w = tid >> 2;            // 0..63
    const int c8 = (tid & 3) * 8;        // halves: 0,8,16,24
    const __half* Ag0 = A + (size_t)(bm + r0w) * K + c8;
    const __half* Ag1 = Ag0 + (size_t)64 * K;
    const __half* Bg0 = Bt + (size_t)(bn + r0w) * K + c8;
    const __half* Bg1 = Bg0 + (size_t)64 * K;
    const uint32_t offA0 = (r0w * HSTR + c8) * 2;
    const uint32_t offA1 = ((r0w + 64) * HSTR + c8) * 2;
    const uint32_t offB0 = 128 * HSTR * 2 + offA0;
    const uint32_t offB1 = 128 * HSTR * 2 + offA1;

    const uint32_t a_row = (lane & 7) + ((lane >> 3) & 1) * 8;
    const uint32_t a_c8 = (lane >> 4) * 8;
    const uint32_t b_row = (lane & 7) + ((lane >> 4) & 1) * 8;
    const uint32_t b_c8 = ((lane >> 3) & 1) * 8;

    const uint32_t aAddr0 = sbase + ((wm * 64 + a_row) * HSTR + a_c8) * 2;
    const uint32_t bAddr0 = sbase + (128 * HSTR + (wn * 32 + b_row) * HSTR + b_c8) * 2;

    const int nchunks = K / 32;

    // Prologue: chunks 0..3 into stages 0..3
#pragma unroll
    for (int s = 0; s < 4; s++) {
        uint32_t so = sbase + s * HSTAGE_BYTES;
        cp16(so + offA0, Ag0 + s * 32);
        cp16(so + offA1, Ag1 + s * 32);
        cp16(so + offB0, Bg0 + s * 32);
        cp16(so + offB1, Bg1 + s * 32);
        cp_commit();
    }

    float acc[4][4][4] = {};
    int cur = 0, nxt = 4;

    for (int c = 0; c < nchunks; c++) {
        cp_wait3();        // chunk c landed (3 newer groups may pend)
        __syncthreads();   // visible; all warps done with stage (c-1)%5

        // Issue chunk c+4 into the stage freed at the barrier
        if (c + 4 < nchunks) {
            uint32_t so = sbase + nxt * HSTAGE_BYTES;
            const int k0 = (c + 4) * 32;
            cp16(so + offA0, Ag0 + k0);
            cp16(so + offA1, Ag1 + k0);
            cp16(so + offB0, Bg0 + k0);
            cp16(so + offB1, Bg1 + k0);
        }
        cp_commit();
        nxt = (nxt + 1 == NSTG) ? 0 : nxt + 1;

        const uint32_t st = cur * HSTAGE_BYTES;
        cur = (cur + 1 == NSTG) ? 0 : cur + 1;

#pragma unroll
        for (int ks = 0; ks < 32; ks += 16) {
            uint32_t afr[4][4];
#pragma unroll
            for (int i = 0; i < 4; i++)
                ldsm4(afr[i], aAddr0 + st + (i * 16 * HSTR + ks) * 2);
            uint32_t bfr[2][4];
#pragma unroll
            for (int jp = 0; jp < 2; jp++)
                ldsm4(bfr[jp], bAddr0 + st + (jp * 16 * HSTR + ks) * 2);
#pragma unroll
            for (int i = 0; i < 4; i++)
#pragma unroll
                for (int jp = 0; jp < 2; jp++) {
                    mma_f16(acc[i][jp * 2],     afr[i], bfr[jp]);
                    mma_f16(acc[i][jp * 2 + 1], afr[i], bfr[jp] + 2);
                }
        }
    }

#pragma unroll
    for (int i = 0; i < 4; i++) {
        const int r0 = bm + wm * 64 + i * 16 + g;
#pragma unroll
        for (int j = 0; j < 4; j++) {
            const int c0 = bn + wn * 32 + j * 8 + tig * 2;
            float bx = 0.f, by = 0.f;
            if (bias) { bx = bias[c0]; by = bias[c0 + 1]; }
            if (HOUT) {
                __half* C = (__half*)Cv;
                uint32_t o0 = packh2(acc[i][j][0] + bx, acc[i][j][1] + by);
                uint32_t o1 = packh2(acc[i][j][2] + bx, acc[i][j][3] + by);
                *(uint32_t*)&C[(size_t)r0 * N + c0] = o0;
                *(uint32_t*)&C[(size_t)(r0 + 8) * N + c0] = o1;
            } else {
                float* C = (float*)Cv;
                *(float2*)&C[(size_t)r0 * N + c0] =
                    make_float2(acc[i][j][0] + bx, acc[i][j][1] + by);
                *(float2*)&C[(size_t)(r0 + 8) * N + c0] =
                    make_float2(acc[i][j][2] + bx, acc[i][j][3] + by);
            }
        }
    }
}

// ---------------------------------------------------------------------------
// Prep: fp32->fp16 copy; transpose to fp16 (src[K,N] -> dst[N,K])
// ---------------------------------------------------------------------------
__global__ __launch_bounds__(256) void f2h_kernel(
    const float* __restrict__ src, __half* __restrict__ dst)
{
    int i = blockIdx.x * 256 + threadIdx.x;
    float4 v = ((const float4*)src)[i];
    ((__half2*)dst)[2 * i]     = __floats2half2_rn(v.x, v.y);
    ((__half2*)dst)[2 * i + 1] = __floats2half2_rn(v.z, v.w);
}

__global__ __launch_bounds__(256) void transpose_h_kernel(
    const float* __restrict__ src, __half* __restrict__ dst, int K, int N)
{
    __shared__ float t[32][33];
    int n0 = blockIdx.x * 32, k0 = blockIdx.y * 32;
    int x = threadIdx.x & 31, y = threadIdx.x >> 5;   // 32 x 8
#pragma unroll
    for (int i = 0; i < 4; i++)
        t[y + i * 8][x] = src[(size_t)(k0 + y + i * 8) * N + n0 + x];
    __syncthreads();
#pragma unroll
    for (int i = 0; i < 4; i++)
        dst[(size_t)(n0 + y + i * 8) * K + k0 + x] = __float2half_rn(t[x][y + i * 8]);
}

// ---------------------------------------------------------------------------
// RoPE: qkv fp16 -> Q/K/V fp16, coalesced [bh][t][d]. Q pre-scaled 1/8.
// ---------------------------------------------------------------------------
__global__ __launch_bounds__(256) void rope_kernel(
    const __half* __restrict__ qkv,
    __half* __restrict__ Q, __half* __restrict__ K, __half* __restrict__ Vh)
{
    const int bt = blockIdx.x;
    const int b = bt >> 11;
    const int t = bt & 2047;
    const __half* row = qkv + (size_t)bt * (3 * HDIM);
    const float LN1E4_OVER_32 = 0.28782313662425575f;  // ln(10000)/32

#pragma unroll
    for (int it = 0; it < 4; it++) {
        int idx = it * 256 + threadIdx.x;
        int h = idx >> 6;
        int d = idx & 63;
        const __half* base = row + h * (3 * HD);
        float qv = __half2float(base[d]);
        float kv = __half2float(base[HD + d]);
        __half vv = base[2 * HD + d];
        int fi = d & 31;
        float inv = expf(-(float)fi * LN1E4_OVER_32);
        float ang = (float)t * inv;
        float sv, cv;
        sincosf(ang, &sv, &cv);
        float qrot = (d < 32) ? -__half2float(base[d + 32]) : __half2float(base[d - 32]);
        float krot = (d < 32) ? -__half2float(base[HD + d + 32]) : __half2float(base[HD + d - 32]);
        int bh = b * NHEAD + h;
        size_t o = ((size_t)bh * T_SEQ + t) * HD + d;
        Q[o] = __float2half_rn((qv * cv + qrot * sv) * 0.125f);
        K[o] = __float2half_rn(kv * cv + krot * sv);
        Vh[o] = vv;
    }
}

// ---------------------------------------------------------------------------
// Flash attention, all-fp16 MMA, double-buffered K/V, ONE barrier + ONE
// wait0 per key block (group jb+1 issued at top of iter jb, full iteration
// of latency hiding).
// ---------------------------------------------------------------------------
#define QHS 72    // half row stride (144B), conflict-free for ldsm/ldsm.trans
#define ATT_SMEM ((128 + 2 * 64 + 2 * 64) * QHS * 2 + 2 * 64 * 4)

__global__ __launch_bounds__(256, 2) void attn_mma_kernel(
    const __half* __restrict__ Q, const __half* __restrict__ K,
    const __half* __restrict__ Vh, const int* __restrict__ amask,
    __half* __restrict__ out)
{
    extern __shared__ __align__(128) char smc[];
    __half* Qs = (__half*)smc;               // [128][QHS]
    __half* Ks = Qs + 128 * QHS;             // [2][64][QHS]
    __half* Vs = Ks + 2 * 64 * QHS;          // [2][64][QHS]
    int* smask = (int*)(Vs + 2 * 64 * QHS);  // [2][64]

    const uint32_t qsb = (uint32_t)__cvta_generic_to_shared(Qs);
    const uint32_t ksb = (uint32_t)__cvta_generic_to_shared(Ks);
    const uint32_t vsb = (uint32_t)__cvta_generic_to_shared(Vs);

    const int tid = threadIdx.x, lane = tid & 31, w = tid >> 5;
    const int g = lane >> 2, tig = lane & 3;
    const int qb = gridDim.x - 1 - blockIdx.x;   // heavy CTAs first
    const int bh = blockIdx.y;
    const int b = bh >> 4, h = bh & 15;

    // Live key-block count (padding is a prefix mask)
    int livev = (amask[b * T_SEQ + lane * 64] != 0) ? 1 : 0;
    unsigned liveb = __ballot_sync(0xffffffff, livev);
    const int nlive = __popc(liveb);

    // ldmatrix per-lane offsets (halves)
    const uint32_t a_row = (lane & 7) + ((lane >> 3) & 1) * 8;
    const uint32_t a_c8 = (lane >> 4) * 8;
    const uint32_t b_row = (lane & 7) + ((lane >> 4) & 1) * 8;
    const uint32_t b_c8 = ((lane >> 3) & 1) * 8;

    const uint32_t qAddr0 = qsb + ((w * 16 + a_row) * QHS + a_c8) * 2;
    const uint32_t kAddr0 = ksb + (b_row * QHS + b_c8) * 2;

    const uint32_t v_row = lane & 15;
    const uint32_t v_c8 = (lane >> 4) * 8;
    const uint32_t vAddr0 = vsb + (v_row * QHS + v_c8) * 2;

    const uint32_t KSTG = 64 * QHS * 2;   // bytes per K/V stage

    // cp.async tile mapping for 64x64-half tiles (2 per thread)
    const int tr = tid >> 3, tc8 = (tid & 7) << 3;    // rows 0..31 (+32)

    // Prologue: Q (group) + KV(0) (group)
    const __half* Qg = Q + ((size_t)bh * T_SEQ + qb * 128) * HD;
#pragma unroll
    for (int it = 0; it < 4; it++) {
        int idx = it * 256 + tid;
        int r = idx >> 3, c8 = (idx & 7) << 3;
        cp16(qsb + (r * QHS + c8) * 2, Qg + r * HD + c8);
    }
    cp_commit();

    const __half* Kbase = K + (size_t)bh * T_SEQ * HD;
    const __half* Vbase = Vh + (size_t)bh * T_SEQ * HD;

    {
        cp16(ksb + (tr * QHS + tc8) * 2, Kbase + tr * HD + tc8);
        cp16(ksb + ((tr + 32) * QHS + tc8) * 2, Kbase + (size_t)(tr + 32) * HD + tc8);
        cp16(vsb + (tr * QHS + tc8) * 2, Vbase + tr * HD + tc8);
        cp16(vsb + ((tr + 32) * QHS + tc8) * 2, Vbase + (size_t)(tr + 32) * HD + tc8);
    }
    if (tid < 64) smask[tid] = amask[b * T_SEQ + tid];
    cp_commit();

    float accO[8][4] = {};
    float m0 = -1e30f, m1 = -1e30f, l0 = 0.f, l1 = 0.f;

    const int qrow0 = qb * 128 + w * 16 + g;
    const int qrow1 = qrow0 + 8;
    const int nkb = 2 * qb + 2;
    const int jb_end = (nkb < nlive) ? nkb : nlive;

    for (int jb = 0; jb < jb_end; jb++) {
        const uint32_t s = (jb & 1) * KSTG;
        const uint32_t sn = ((jb + 1) & 1) * KSTG;

        // 1) group(jb) landed (issued a full iteration ago)
        cp_wait0();
        __syncthreads();   // visible; all warps done with stage (jb-1)&1

        // 2) issue group(jb+1) into the freed stage
        if (jb + 1 < jb_end) {
            const __half* Kg = Kbase + (size_t)(jb + 1) * 64 * HD;
            const __half* Vg = Vbase + (size_t)(jb + 1) * 64 * HD;
            cp16(ksb + sn + (tr * QHS + tc8) * 2, Kg + tr * HD + tc8);
            cp16(ksb + sn + ((tr + 32) * QHS + tc8) * 2, Kg + (size_t)(tr + 32) * HD + tc8);
            cp16(vsb + sn + (tr * QHS + tc8) * 2, Vg + tr * HD + tc8);
            cp16(vsb + sn + ((tr + 32) * QHS + tc8) * 2, Vg + (size_t)(tr + 32) * HD + tc8);
            if (tid < 64) smask[((jb + 1) & 1) * 64 + tid] = amask[b * T_SEQ + (jb + 1) * 64 + tid];
        }
        cp_commit();

        const int* msk = smask + (jb & 1) * 64;

        // 3) S = Q_tile @ K_tile^T (fp16 m16n8k16)
        float sacc[8][4];
#pragma unroll
        for (int j = 0; j < 8; j++)
            sacc[j][0] = sacc[j][1] = sacc[j][2] = sacc[j][3] = 0.f;
#pragma unroll
        for (int ks = 0; ks < 64; ks += 16) {
            uint32_t af[4];
            ldsm4(af, qAddr0 + ks * 2);
#pragma unroll
            for (int jp = 0; jp < 4; jp++) {
                uint32_t bf[4];
                ldsm4(bf, kAddr0 + s + (jp * 16 * QHS + ks) * 2);
                mma_f16(sacc[jp * 2],     af, bf);
                mma_f16(sacc[jp * 2 + 1], af, bf + 2);
            }
        }

        // 4) mask + online softmax; P packed to fp16 pairs in registers
        float mx0 = m0, mx1 = m1;
#pragma unroll
        for (int j = 0; j < 8; j++) {
            int c = j * 8 + 2 * tig;
            int colg = jb * 64 + c;
            bool v0 = msk[c]     && (colg     <= qrow0);
            bool v1 = msk[c + 1] && (colg + 1 <= qrow0);
            bool v2 = msk[c]     && (colg     <= qrow1);
            bool v3 = msk[c + 1] && (colg + 1 <= qrow1);
            sacc[j][0] = v0 ? sacc[j][0] : -1e30f;
            sacc[j][1] = v1 ? sacc[j][1] : -1e30f;
            sacc[j][2] = v2 ? sacc[j][2] : -1e30f;
            sacc[j][3] = v3 ? sacc[j][3] : -1e30f;
            mx0 = fmaxf(mx0, fmaxf(sacc[j][0], sacc[j][1]));
            mx1 = fmaxf(mx1, fmaxf(sacc[j][2], sacc[j][3]));
        }
        mx0 = fmaxf(mx0, __shfl_xor_sync(0xffffffff, mx0, 1));
        mx0 = fmaxf(mx0, __shfl_xor_sync(0xffffffff, mx0, 2));
        mx1 = fmaxf(mx1, __shfl_xor_sync(0xffffffff, mx1, 1));
        mx1 = fmaxf(mx1, __shfl_xor_sync(0xffffffff, mx1, 2));
        float corr0 = __expf(m0 - mx0);
        float corr1 = __expf(m1 - mx1);
        m0 = mx0; m1 = mx1;

        uint32_t ph[8][2];
        float sum0 = 0.f, sum1 = 0.f;
#pragma unroll
        for (int j = 0; j < 8; j++) {
            float p0 = __expf(sacc[j][0] - mx0);
            float p1 = __expf(sacc[j][1] - mx0);
            float p2 = __expf(sacc[j][2] - mx1);
            float p3 = __expf(sacc[j][3] - mx1);
            ph[j][0] = packh2(p0, p1);
            ph[j][1] = packh2(p2, p3);
            float2 f0 = __half22float2(*(__half2*)&ph[j][0]);
            float2 f1 = __half22float2(*(__half2*)&ph[j][1]);
            sum0 += f0.x + f0.y;
            sum1 += f1.x + f1.y;
        }
        sum0 += __shfl_xor_sync(0xffffffff, sum0, 1);
        sum0 += __shfl_xor_sync(0xffffffff, sum0, 2);
        sum1 += __shfl_xor_sync(0xffffffff, sum1, 1);
        sum1 += __shfl_xor_sync(0xffffffff, sum1, 2);
        l0 = l0 * corr0 + sum0;
        l1 = l1 * corr1 + sum1;

#pragma unroll
        for (int j = 0; j < 8; j++) {
            accO[j][0] *= corr0; accO[j][1] *= corr0;
            accO[j][2] *= corr1; accO[j][3] *= corr1;
        }

        // 5) PV from Vs[s] (resident since the top wait)
#pragma unroll
        for (int kk = 0; kk < 4; kk++) {
            uint32_t pa[4] = { ph[2 * kk][0], ph[2 * kk][1],
                               ph[2 * kk + 1][0], ph[2 * kk + 1][1] };
#pragma unroll
            for (int jp = 0; jp < 4; jp++) {
                uint32_t bf[4];
                ldsm4t(bf, vAddr0 + s + (kk * 16 * QHS + jp * 16) * 2);
                mma_f16(accO[jp * 2],     pa, bf);
                mma_f16(accO[jp * 2 + 1], pa, bf + 2);
            }
        }
    }

    // ---- epilogue: fp16 output ----
    float inv0 = 1.f / l0, inv1 = 1.f / l1;
    const int r0 = b * T_SEQ + qb * 128 + w * 16 + g;
#pragma unroll
    for (int j = 0; j < 8; j++) {
        int c = h * HD + j * 8 + 2 * tig;
        uint32_t o0 = packh2(accO[j][0] * inv0, accO[j][1] * inv0);
        uint32_t o1 = packh2(accO[j][2] * inv1, accO[j][3] * inv1);
        *(uint32_t*)&out[(size_t)r0 * HDIM + c] = o0;
        *(uint32_t*)&out[(size_t)(r0 + 8) * HDIM + c] = o1;
    }
}

// ---------------------------------------------------------------------------
// Launch
// ---------------------------------------------------------------------------
extern "C" void kernel_launch(void* const* d_in, const int* in_sizes, int n_in,
                              void* d_out, int out_size)
{
    const float* hidden = (const float*)d_in[0];
    const int*   amask  = (const int*)d_in[1];
    const float* w_qkv  = (const float*)d_in[2];
    const float* b_qkv  = (const float*)d_in[3];
    const float* w_out  = (const float*)d_in[4];
    float* out = (float*)d_out;

    __half *qkvh, *hh, *Qh, *Kh, *Vh, *attn, *Bt1, *Bt2;
    cudaGetSymbolAddress((void**)&qkvh, g_qkvh);
    cudaGetSymbolAddress((void**)&hh,   g_hh);
    cudaGetSymbolAddress((void**)&Qh,   g_Qh);
    cudaGetSymbolAddress((void**)&Kh,   g_Kh);
    cudaGetSymbolAddress((void**)&Vh,   g_Vh);
    cudaGetSymbolAddress((void**)&attn, g_attn);
    cudaGetSymbolAddress((void**)&Bt1,  g_Bt1);
    cudaGetSymbolAddress((void**)&Bt2,  g_Bt2);

    cudaFuncSetAttribute(h16_mma_gemm<true>, cudaFuncAttributeMaxDynamicSharedMemorySize,
                         HGEMM_SMEM);
    cudaFuncSetAttribute(h16_mma_gemm<false>, cudaFuncAttributeMaxDynamicSharedMemorySize,
                         HGEMM_SMEM);
    cudaFuncSetAttribute(attn_mma_kernel, cudaFuncAttributeMaxDynamicSharedMemorySize,
                         ATT_SMEM);

    // 0) prep: hidden->fp16; weights transpose->fp16
    f2h_kernel<<<MROWS * HDIM / 4 / 256, 256>>>(hidden, hh);
    transpose_h_kernel<<<dim3(3 * HDIM / 32, HDIM / 32), 256>>>(w_qkv, Bt1, HDIM, 3 * HDIM);
    transpose_h_kernel<<<dim3(HDIM / 32, HDIM / 32), 256>>>(w_out, Bt2, HDIM, HDIM);

    // 1) qkv = hidden @ w_qkv + b_qkv -> fp16
    h16_mma_gemm<true><<<dim3(3 * HDIM / 128, MROWS / 128), 256, HGEMM_SMEM>>>(
        hh, Bt1, b_qkv, qkvh, 3 * HDIM, HDIM);

    // 2) RoPE -> fp16 Q/K/V
    rope_kernel<<<MROWS, 256>>>(qkvh, Qh, Kh, Vh);

    // 3) flash attention -> attn fp16
    attn_mma_kernel<<<dim3(T_SEQ / 128, BATCH * NHEAD), 256, ATT_SMEM>>>(
        Qh, Kh, Vh, amask, attn);

    // 4) out = attn @ w_out -> fp32
    h16_mma_gemm<false><<<dim3(HDIM / 128, MROWS / 128), 256, HGEMM_SMEM>>>(
        attn, Bt2, nullptr, out, HDIM, HDIM);
}

// round 13
// speedup vs baseline: 1.0319x; 1.0319x over previous
#include <cuda_runtime.h>
#include <cuda_fp16.h>
#include <cstdint>
#include <cstddef>

// Problem constants
#define T_SEQ  2048
#define NHEAD  16
#define HDIM   1024
#define HD     64
#define BATCH  2
#define MROWS  (BATCH * T_SEQ)   // 4096

// Scratch (device globals; no allocations allowed)
__device__ __half g_qkvh[MROWS * 3 * HDIM];           // qkv fp16
__device__ __half g_hh[MROWS * HDIM];                 // hidden fp16
__device__ __half g_Qh[BATCH * NHEAD * T_SEQ * HD];   // [bh][t][d], fp16, pre-scaled
__device__ __half g_Kh[BATCH * NHEAD * T_SEQ * HD];   // [bh][t][d], fp16
__device__ __half g_Vh[BATCH * NHEAD * T_SEQ * HD];   // [bh][t][d], fp16
__device__ __half g_attn[MROWS * HDIM];               // attention output fp16
__device__ __half g_Bt1[3 * HDIM * HDIM];             // w_qkv^T fp16 [3072,1024]
__device__ __half g_Bt2[HDIM * HDIM];                 // w_out^T fp16 [1024,1024]

// ---------------------------------------------------------------------------
// Helpers
// ---------------------------------------------------------------------------
__device__ __forceinline__ uint32_t packh2(float lo, float hi) {
    uint32_t r;
    asm("cvt.rn.f16x2.f32 %0, %1, %2;" : "=r"(r) : "f"(hi), "f"(lo));
    return r;
}

__device__ __forceinline__ void cp16(uint32_t dst, const void* src) {
    asm volatile("cp.async.cg.shared.global [%0], [%1], 16;\n" :: "r"(dst), "l"(src));
}
__device__ __forceinline__ void cp_commit() {
    asm volatile("cp.async.commit_group;\n");
}
__device__ __forceinline__ void cp_wait3() {
    asm volatile("cp.async.wait_group 3;\n");
}
__device__ __forceinline__ void cp_wait0() {
    asm volatile("cp.async.wait_group 0;\n");
}

__device__ __forceinline__ void mma_f16(float* c, const uint32_t* a, const uint32_t* b) {
    asm volatile(
        "mma.sync.aligned.m16n8k16.row.col.f32.f16.f16.f32 "
        "{%0,%1,%2,%3}, {%4,%5,%6,%7}, {%8,%9}, {%0,%1,%2,%3};"
        : "+f"(c[0]), "+f"(c[1]), "+f"(c[2]), "+f"(c[3])
        : "r"(a[0]), "r"(a[1]), "r"(a[2]), "r"(a[3]), "r"(b[0]), "r"(b[1]));
}

__device__ __forceinline__ void ldsm4(uint32_t* r, uint32_t addr) {
    asm volatile("ldmatrix.sync.aligned.m8n8.x4.shared.b16 {%0,%1,%2,%3}, [%4];"
        : "=r"(r[0]), "=r"(r[1]), "=r"(r[2]), "=r"(r[3]) : "r"(addr));
}

__device__ __forceinline__ void ldsm4t(uint32_t* r, uint32_t addr) {
    asm volatile("ldmatrix.sync.aligned.m8n8.x4.trans.shared.b16 {%0,%1,%2,%3}, [%4];"
        : "=r"(r[0]), "=r"(r[1]), "=r"(r[2]), "=r"(r[3]) : "r"(addr));
}

// ---------------------------------------------------------------------------
// fp16 mma.sync GEMM — PROVEN round-11 mainloop: 4-stage, wait3, two barriers
// per chunk, cp.async issued AFTER the MMAs. C = Ah @ Bth^T (+bias).
// 128x128x32 CTA chunk, 256 threads, 8 warps (2x4), warp tile 64x32.
// HOUT: write __half output, else float.
// ---------------------------------------------------------------------------
#define HSTR 40                            // halves per smem row (32 + 8 pad), 80B
#define HSTAGE_BYTES (2 * 128 * HSTR * 2)  // A tile then B tile = 20480
#define HGEMM_SMEM (4 * HSTAGE_BYTES)      // 81920

template<bool HOUT>
__global__ __launch_bounds__(256) void h16_mma_gemm(
    const __half* __restrict__ A, const __half* __restrict__ Bt,
    const float* __restrict__ bias, void* __restrict__ Cv,
    int N, int K)
{
    extern __shared__ __align__(128) char smc[];
    const uint32_t sbase = (uint32_t)__cvta_generic_to_shared(smc);

    const int tid = threadIdx.x, lane = tid & 31, w = tid >> 5;
    const int wm = w & 1, wn = w >> 1;           // warp 2x4 grid
    const int g = lane >> 2, tig = lane & 3;
    const int bm = blockIdx.y * 128, bn = blockIdx.x * 128;

    const int r0w = tid >> 2;            // 0..63
    const int c8 = (tid & 3) * 8;        // halves: 0,8,16,24
    const __half* Ag0 = A + (size_t)(bm + r0w) * K + c8;
    const __half* Ag1 = Ag0 + (size_t)64 * K;
    const __half* Bg0 = Bt + (size_t)(bn + r0w) * K + c8;
    const __half* Bg1 = Bg0 + (size_t)64 * K;
    const uint32_t offA0 = (r0w * HSTR + c8) * 2;
    const uint32_t offA1 = ((r0w + 64) * HSTR + c8) * 2;
    const uint32_t offB0 = 128 * HSTR * 2 + offA0;
    const uint32_t offB1 = 128 * HSTR * 2 + offA1;

    const uint32_t a_row = (lane & 7) + ((lane >> 3) & 1) * 8;
    const uint32_t a_c8 = (lane >> 4) * 8;
    const uint32_t b_row = (lane & 7) + ((lane >> 4) & 1) * 8;
    const uint32_t b_c8 = ((lane >> 3) & 1) * 8;

    const uint32_t aAddr0 = sbase + ((wm * 64 + a_row) * HSTR + a_c8) * 2;
    const uint32_t bAddr0 = sbase + (128 * HSTR + (wn * 32 + b_row) * HSTR + b_c8) * 2;

    const int nchunks = K / 32;

    // Prologue: fill 4 stages (prefetch distance 4)
#pragma unroll
    for (int s = 0; s < 4; s++) {
        uint32_t so = sbase + s * HSTAGE_BYTES;
        cp16(so + offA0, Ag0 + s * 32);
        cp16(so + offA1, Ag1 + s * 32);
        cp16(so + offB0, Bg0 + s * 32);
        cp16(so + offB1, Bg1 + s * 32);
        cp_commit();
    }

    float acc[4][4][4] = {};

    for (int c = 0; c < nchunks; c++) {
        cp_wait3();
        __syncthreads();

        const uint32_t st = (c & 3) * HSTAGE_BYTES;

#pragma unroll
        for (int ks = 0; ks < 32; ks += 16) {
            uint32_t afr[4][4];
#pragma unroll
            for (int i = 0; i < 4; i++)
                ldsm4(afr[i], aAddr0 + st + (i * 16 * HSTR + ks) * 2);
            uint32_t bfr[2][4];
#pragma unroll
            for (int jp = 0; jp < 2; jp++)
                ldsm4(bfr[jp], bAddr0 + st + (jp * 16 * HSTR + ks) * 2);
#pragma unroll
            for (int i = 0; i < 4; i++)
#pragma unroll
                for (int jp = 0; jp < 2; jp++) {
                    mma_f16(acc[i][jp * 2],     afr[i], bfr[jp]);
                    mma_f16(acc[i][jp * 2 + 1], afr[i], bfr[jp] + 2);
                }
        }
        __syncthreads();

        if (c + 4 < nchunks) {
            uint32_t so = sbase + (c & 3) * HSTAGE_BYTES;
            const int k0 = (c + 4) * 32;
            cp16(so + offA0, Ag0 + k0);
            cp16(so + offA1, Ag1 + k0);
            cp16(so + offB0, Bg0 + k0);
            cp16(so + offB1, Bg1 + k0);
        }
        cp_commit();
    }

#pragma unroll
    for (int i = 0; i < 4; i++) {
        const int r0 = bm + wm * 64 + i * 16 + g;
#pragma unroll
        for (int j = 0; j < 4; j++) {
            const int c0 = bn + wn * 32 + j * 8 + tig * 2;
            float bx = 0.f, by = 0.f;
            if (bias) { bx = bias[c0]; by = bias[c0 + 1]; }
            if (HOUT) {
                __half* C = (__half*)Cv;
                uint32_t o0 = packh2(acc[i][j][0] + bx, acc[i][j][1] + by);
                uint32_t o1 = packh2(acc[i][j][2] + bx, acc[i][j][3] + by);
                *(uint32_t*)&C[(size_t)r0 * N + c0] = o0;
                *(uint32_t*)&C[(size_t)(r0 + 8) * N + c0] = o1;
            } else {
                float* C = (float*)Cv;
                *(float2*)&C[(size_t)r0 * N + c0] =
                    make_float2(acc[i][j][0] + bx, acc[i][j][1] + by);
                *(float2*)&C[(size_t)(r0 + 8) * N + c0] =
                    make_float2(acc[i][j][2] + bx, acc[i][j][3] + by);
            }
        }
    }
}

// ---------------------------------------------------------------------------
// Prep: fp32->fp16 copy; transpose to fp16 (src[K,N] -> dst[N,K])
// ---------------------------------------------------------------------------
__global__ __launch_bounds__(256) void f2h_kernel(
    const float* __restrict__ src, __half* __restrict__ dst)
{
    int i = blockIdx.x * 256 + threadIdx.x;
    float4 v = ((const float4*)src)[i];
    ((__half2*)dst)[2 * i]     = __floats2half2_rn(v.x, v.y);
    ((__half2*)dst)[2 * i + 1] = __floats2half2_rn(v.z, v.w);
}

__global__ __launch_bounds__(256) void transpose_h_kernel(
    const float* __restrict__ src, __half* __restrict__ dst, int K, int N)
{
    __shared__ float t[32][33];
    int n0 = blockIdx.x * 32, k0 = blockIdx.y * 32;
    int x = threadIdx.x & 31, y = threadIdx.x >> 5;   // 32 x 8
#pragma unroll
    for (int i = 0; i < 4; i++)
        t[y + i * 8][x] = src[(size_t)(k0 + y + i * 8) * N + n0 + x];
    __syncthreads();
#pragma unroll
    for (int i = 0; i < 4; i++)
        dst[(size_t)(n0 + y + i * 8) * K + k0 + x] = __float2half_rn(t[x][y + i * 8]);
}

// ---------------------------------------------------------------------------
// RoPE: qkv fp16 -> Q/K/V fp16, coalesced [bh][t][d]. Q pre-scaled 1/8.
// ---------------------------------------------------------------------------
__global__ __launch_bounds__(256) void rope_kernel(
    const __half* __restrict__ qkv,
    __half* __restrict__ Q, __half* __restrict__ K, __half* __restrict__ Vh)
{
    const int bt = blockIdx.x;
    const int b = bt >> 11;
    const int t = bt & 2047;
    const __half* row = qkv + (size_t)bt * (3 * HDIM);
    const float LN1E4_OVER_32 = 0.28782313662425575f;  // ln(10000)/32

#pragma unroll
    for (int it = 0; it < 4; it++) {
        int idx = it * 256 + threadIdx.x;
        int h = idx >> 6;
        int d = idx & 63;
        const __half* base = row + h * (3 * HD);
        float qv = __half2float(base[d]);
        float kv = __half2float(base[HD + d]);
        __half vv = base[2 * HD + d];
        int fi = d & 31;
        float inv = expf(-(float)fi * LN1E4_OVER_32);
        float ang = (float)t * inv;
        float sv, cv;
        sincosf(ang, &sv, &cv);
        float qrot = (d < 32) ? -__half2float(base[d + 32]) : __half2float(base[d - 32]);
        float krot = (d < 32) ? -__half2float(base[HD + d + 32]) : __half2float(base[HD + d - 32]);
        int bh = b * NHEAD + h;
        size_t o = ((size_t)bh * T_SEQ + t) * HD + d;
        Q[o] = __float2half_rn((qv * cv + qrot * sv) * 0.125f);
        K[o] = __float2half_rn(kv * cv + krot * sv);
        Vh[o] = vv;
    }
}

// ---------------------------------------------------------------------------
// Flash attention, all-fp16 MMA, double-buffered K/V, one barrier + one
// wait0 per key block (group jb+1 issued at top of iter jb).
// ---------------------------------------------------------------------------
#define QHS 72    // half row stride (144B), conflict-free for ldsm/ldsm.trans
#define ATT_SMEM ((128 + 2 * 64 + 2 * 64) * QHS * 2 + 2 * 64 * 4)

__global__ __launch_bounds__(256, 2) void attn_mma_kernel(
    const __half* __restrict__ Q, const __half* __restrict__ K,
    const __half* __restrict__ Vh, const int* __restrict__ amask,
    __half* __restrict__ out)
{
    extern __shared__ __align__(128) char smc[];
    __half* Qs = (__half*)smc;               // [128][QHS]
    __half* Ks = Qs + 128 * QHS;             // [2][64][QHS]
    __half* Vs = Ks + 2 * 64 * QHS;          // [2][64][QHS]
    int* smask = (int*)(Vs + 2 * 64 * QHS);  // [2][64]

    const uint32_t qsb = (uint32_t)__cvta_generic_to_shared(Qs);
    const uint32_t ksb = (uint32_t)__cvta_generic_to_shared(Ks);
    const uint32_t vsb = (uint32_t)__cvta_generic_to_shared(Vs);

    const int tid = threadIdx.x, lane = tid & 31, w = tid >> 5;
    const int g = lane >> 2, tig = lane & 3;
    const int qb = gridDim.x - 1 - blockIdx.x;   // heavy CTAs first
    const int bh = blockIdx.y;
    const int b = bh >> 4, h = bh & 15;

    // Live key-block count (padding is a prefix mask)
    int livev = (amask[b * T_SEQ + lane * 64] != 0) ? 1 : 0;
    unsigned liveb = __ballot_sync(0xffffffff, livev);
    const int nlive = __popc(liveb);

    // ldmatrix per-lane offsets (halves)
    const uint32_t a_row = (lane & 7) + ((lane >> 3) & 1) * 8;
    const uint32_t a_c8 = (lane >> 4) * 8;
    const uint32_t b_row = (lane & 7) + ((lane >> 4) & 1) * 8;
    const uint32_t b_c8 = ((lane >> 3) & 1) * 8;

    const uint32_t qAddr0 = qsb + ((w * 16 + a_row) * QHS + a_c8) * 2;
    const uint32_t kAddr0 = ksb + (b_row * QHS + b_c8) * 2;

    const uint32_t v_row = lane & 15;
    const uint32_t v_c8 = (lane >> 4) * 8;
    const uint32_t vAddr0 = vsb + (v_row * QHS + v_c8) * 2;

    const uint32_t KSTG = 64 * QHS * 2;   // bytes per K/V stage

    const int tr = tid >> 3, tc8 = (tid & 7) << 3;    // rows 0..31 (+32)

    // Prologue: Q (group) + KV(0) (group)
    const __half* Qg = Q + ((size_t)bh * T_SEQ + qb * 128) * HD;
#pragma unroll
    for (int it = 0; it < 4; it++) {
        int idx = it * 256 + tid;
        int r = idx >> 3, c8 = (idx & 7) << 3;
        cp16(qsb + (r * QHS + c8) * 2, Qg + r * HD + c8);
    }
    cp_commit();

    const __half* Kbase = K + (size_t)bh * T_SEQ * HD;
    const __half* Vbase = Vh + (size_t)bh * T_SEQ * HD;

    {
        cp16(ksb + (tr * QHS + tc8) * 2, Kbase + tr * HD + tc8);
        cp16(ksb + ((tr + 32) * QHS + tc8) * 2, Kbase + (size_t)(tr + 32) * HD + tc8);
        cp16(vsb + (tr * QHS + tc8) * 2, Vbase + tr * HD + tc8);
        cp16(vsb + ((tr + 32) * QHS + tc8) * 2, Vbase + (size_t)(tr + 32) * HD + tc8);
    }
    if (tid < 64) smask[tid] = amask[b * T_SEQ + tid];
    cp_commit();

    float accO[8][4] = {};
    float m0 = -1e30f, m1 = -1e30f, l0 = 0.f, l1 = 0.f;

    const int qrow0 = qb * 128 + w * 16 + g;
    const int qrow1 = qrow0 + 8;
    const int nkb = 2 * qb + 2;
    const int jb_end = (nkb < nlive) ? nkb : nlive;

    for (int jb = 0; jb < jb_end; jb++) {
        const uint32_t s = (jb & 1) * KSTG;
        const uint32_t sn = ((jb + 1) & 1) * KSTG;

        // 1) group(jb) landed (issued a full iteration ago)
        cp_wait0();
        __syncthreads();   // visible; all warps done with stage (jb-1)&1

        // 2) issue group(jb+1) into the freed stage
        if (jb + 1 < jb_end) {
            const __half* Kg = Kbase + (size_t)(jb + 1) * 64 * HD;
            const __half* Vg = Vbase + (size_t)(jb + 1) * 64 * HD;
            cp16(ksb + sn + (tr * QHS + tc8) * 2, Kg + tr * HD + tc8);
            cp16(ksb + sn + ((tr + 32) * QHS + tc8) * 2, Kg + (size_t)(tr + 32) * HD + tc8);
            cp16(vsb + sn + (tr * QHS + tc8) * 2, Vg + tr * HD + tc8);
            cp16(vsb + sn + ((tr + 32) * QHS + tc8) * 2, Vg + (size_t)(tr + 32) * HD + tc8);
            if (tid < 64) smask[((jb + 1) & 1) * 64 + tid] = amask[b * T_SEQ + (jb + 1) * 64 + tid];
        }
        cp_commit();

        const int* msk = smask + (jb & 1) * 64;

        // 3) S = Q_tile @ K_tile^T (fp16 m16n8k16)
        float sacc[8][4];
#pragma unroll
        for (int j = 0; j < 8; j++)
            sacc[j][0] = sacc[j][1] = sacc[j][2] = sacc[j][3] = 0.f;
#pragma unroll
        for (int ks = 0; ks < 64; ks += 16) {
            uint32_t af[4];
            ldsm4(af, qAddr0 + ks * 2);
#pragma unroll
            for (int jp = 0; jp < 4; jp++) {
                uint32_t bf[4];
                ldsm4(bf, kAddr0 + s + (jp * 16 * QHS + ks) * 2);
                mma_f16(sacc[jp * 2],     af, bf);
                mma_f16(sacc[jp * 2 + 1], af, bf + 2);
            }
        }

        // 4) mask + online softmax; P packed to fp16 pairs in registers
        float mx0 = m0, mx1 = m1;
#pragma unroll
        for (int j = 0; j < 8; j++) {
            int c = j * 8 + 2 * tig;
            int colg = jb * 64 + c;
            bool v0 = msk[c]     && (colg     <= qrow0);
            bool v1 = msk[c + 1] && (colg + 1 <= qrow0);
            bool v2 = msk[c]     && (colg     <= qrow1);
            bool v3 = msk[c + 1] && (colg + 1 <= qrow1);
            sacc[j][0] = v0 ? sacc[j][0] : -1e30f;
            sacc[j][1] = v1 ? sacc[j][1] : -1e30f;
            sacc[j][2] = v2 ? sacc[j][2] : -1e30f;
            sacc[j][3] = v3 ? sacc[j][3] : -1e30f;
            mx0 = fmaxf(mx0, fmaxf(sacc[j][0], sacc[j][1]));
            mx1 = fmaxf(mx1, fmaxf(sacc[j][2], sacc[j][3]));
        }
        mx0 = fmaxf(mx0, __shfl_xor_sync(0xffffffff, mx0, 1));
        mx0 = fmaxf(mx0, __shfl_xor_sync(0xffffffff, mx0, 2));
        mx1 = fmaxf(mx1, __shfl_xor_sync(0xffffffff, mx1, 1));
        mx1 = fmaxf(mx1, __shfl_xor_sync(0xffffffff, mx1, 2));
        float corr0 = __expf(m0 - mx0);
        float corr1 = __expf(m1 - mx1);
        m0 = mx0; m1 = mx1;

        uint32_t ph[8][2];
        float sum0 = 0.f, sum1 = 0.f;
#pragma unroll
        for (int j = 0; j < 8; j++) {
            float p0 = __expf(sacc[j][0] - mx0);
            float p1 = __expf(sacc[j][1] - mx0);
            float p2 = __expf(sacc[j][2] - mx1);
            float p3 = __expf(sacc[j][3] - mx1);
            ph[j][0] = packh2(p0, p1);
            ph[j][1] = packh2(p2, p3);
            float2 f0 = __half22float2(*(__half2*)&ph[j][0]);
            float2 f1 = __half22float2(*(__half2*)&ph[j][1]);
            sum0 += f0.x + f0.y;
            sum1 += f1.x + f1.y;
        }
        sum0 += __shfl_xor_sync(0xffffffff, sum0, 1);
        sum0 += __shfl_xor_sync(0xffffffff, sum0, 2);
        sum1 += __shfl_xor_sync(0xffffffff, sum1, 1);
        sum1 += __shfl_xor_sync(0xffffffff, sum1, 2);
        l0 = l0 * corr0 + sum0;
        l1 = l1 * corr1 + sum1;

#pragma unroll
        for (int j = 0; j < 8; j++) {
            accO[j][0] *= corr0; accO[j][1] *= corr0;
            accO[j][2] *= corr1; accO[j][3] *= corr1;
        }

        // 5) PV from Vs[s]
#pragma unroll
        for (int kk = 0; kk < 4; kk++) {
            uint32_t pa[4] = { ph[2 * kk][0], ph[2 * kk][1],
                               ph[2 * kk + 1][0], ph[2 * kk + 1][1] };
#pragma unroll
            for (int jp = 0; jp < 4; jp++) {
                uint32_t bf[4];
                ldsm4t(bf, vAddr0 + s + (kk * 16 * QHS + jp * 16) * 2);
                mma_f16(accO[jp * 2],     pa, bf);
                mma_f16(accO[jp * 2 + 1], pa, bf + 2);
            }
        }
    }

    // ---- epilogue: fp16 output ----
    float inv0 = 1.f / l0, inv1 = 1.f / l1;
    const int r0 = b * T_SEQ + qb * 128 + w * 16 + g;
#pragma unroll
    for (int j = 0; j < 8; j++) {
        int c = h * HD + j * 8 + 2 * tig;
        uint32_t o0 = packh2(accO[j][0] * inv0, accO[j][1] * inv0);
        uint32_t o1 = packh2(accO[j][2] * inv1, accO[j][3] * inv1);
        *(uint32_t*)&out[(size_t)r0 * HDIM + c] = o0;
        *(uint32_t*)&out[(size_t)(r0 + 8) * HDIM + c] = o1;
    }
}

// ---------------------------------------------------------------------------
// Launch
// ---------------------------------------------------------------------------
extern "C" void kernel_launch(void* const* d_in, const int* in_sizes, int n_in,
                              void* d_out, int out_size)
{
    const float* hidden = (const float*)d_in[0];
    const int*   amask  = (const int*)d_in[1];
    const float* w_qkv  = (const float*)d_in[2];
    const float* b_qkv  = (const float*)d_in[3];
    const float* w_out  = (const float*)d_in[4];
    float* out = (float*)d_out;

    __half *qkvh, *hh, *Qh, *Kh, *Vh, *attn, *Bt1, *Bt2;
    cudaGetSymbolAddress((void**)&qkvh, g_qkvh);
    cudaGetSymbolAddress((void**)&hh,   g_hh);
    cudaGetSymbolAddress((void**)&Qh,   g_Qh);
    cudaGetSymbolAddress((void**)&Kh,   g_Kh);
    cudaGetSymbolAddress((void**)&Vh,   g_Vh);
    cudaGetSymbolAddress((void**)&attn, g_attn);
    cudaGetSymbolAddress((void**)&Bt1,  g_Bt1);
    cudaGetSymbolAddress((void**)&Bt2,  g_Bt2);

    cudaFuncSetAttribute(h16_mma_gemm<true>, cudaFuncAttributeMaxDynamicSharedMemorySize,
                         HGEMM_SMEM);
    cudaFuncSetAttribute(h16_mma_gemm<false>, cudaFuncAttributeMaxDynamicSharedMemorySize,
                         HGEMM_SMEM);
    cudaFuncSetAttribute(attn_mma_kernel, cudaFuncAttributeMaxDynamicSharedMemorySize,
                         ATT_SMEM);

    // 0) prep: hidden->fp16; weights transpose->fp16
    f2h_kernel<<<MROWS * HDIM / 4 / 256, 256>>>(hidden, hh);
    transpose_h_kernel<<<dim3(3 * HDIM / 32, HDIM / 32), 256>>>(w_qkv, Bt1, HDIM, 3 * HDIM);
    transpose_h_kernel<<<dim3(HDIM / 32, HDIM / 32), 256>>>(w_out, Bt2, HDIM, HDIM);

    // 1) qkv = hidden @ w_qkv + b_qkv -> fp16
    h16_mma_gemm<true><<<dim3(3 * HDIM / 128, MROWS / 128), 256, HGEMM_SMEM>>>(
        hh, Bt1, b_qkv, qkvh, 3 * HDIM, HDIM);

    // 2) RoPE -> fp16 Q/K/V
    rope_kernel<<<MROWS, 256>>>(qkvh, Qh, Kh, Vh);

    // 3) flash attention -> attn fp16
    attn_mma_kernel<<<dim3(T_SEQ / 128, BATCH * NHEAD), 256, ATT_SMEM>>>(
        Qh, Kh, Vh, amask, attn);

    // 4) out = attn @ w_out -> fp32
    h16_mma_gemm<false><<<dim3(HDIM / 128, MROWS / 128), 256, HGEMM_SMEM>>>(
        attn, Bt2, nullptr, out, HDIM, HDIM);
}

// round 14
// speedup vs baseline: 1.1412x; 1.1059x over previous
#include <cuda_runtime.h>
#include <cuda_fp16.h>
#include <cstdint>
#include <cstddef>

// Problem constants
#define T_SEQ  2048
#define NHEAD  16
#define HDIM   1024
#define HD     64
#define BATCH  2
#define MROWS  (BATCH * T_SEQ)   // 4096

// Scratch (device globals; no allocations allowed)
__device__ __half g_qkvh[MROWS * 3 * HDIM];           // qkv fp16
__device__ __half g_hh[MROWS * HDIM];                 // hidden fp16
__device__ __half g_Qh[BATCH * NHEAD * T_SEQ * HD];   // [bh][t][d], fp16, pre-scaled
__device__ __half g_Kh[BATCH * NHEAD * T_SEQ * HD];   // [bh][t][d], fp16
__device__ __half g_Vh[BATCH * NHEAD * T_SEQ * HD];   // [bh][t][d], fp16
__device__ __half g_attn[MROWS * HDIM];               // attention output fp16
__device__ __half g_B1[HDIM * 3 * HDIM];              // w_qkv fp16 [K=1024][N=3072]
__device__ __half g_B2[HDIM * HDIM];                  // w_out fp16 [K=1024][N=1024]

// ---------------------------------------------------------------------------
// Helpers
// ---------------------------------------------------------------------------
__device__ __forceinline__ uint32_t packh2(float lo, float hi) {
    uint32_t r;
    asm("cvt.rn.f16x2.f32 %0, %1, %2;" : "=r"(r) : "f"(hi), "f"(lo));
    return r;
}

__device__ __forceinline__ void cp16(uint32_t dst, const void* src) {
    asm volatile("cp.async.cg.shared.global [%0], [%1], 16;\n" :: "r"(dst), "l"(src));
}
__device__ __forceinline__ void cp_commit() {
    asm volatile("cp.async.commit_group;\n");
}
__device__ __forceinline__ void cp_wait3() {
    asm volatile("cp.async.wait_group 3;\n");
}
__device__ __forceinline__ void cp_wait0() {
    asm volatile("cp.async.wait_group 0;\n");
}

__device__ __forceinline__ void mma_f16(float* c, const uint32_t* a, const uint32_t* b) {
    asm volatile(
        "mma.sync.aligned.m16n8k16.row.col.f32.f16.f16.f32 "
        "{%0,%1,%2,%3}, {%4,%5,%6,%7}, {%8,%9}, {%0,%1,%2,%3};"
        : "+f"(c[0]), "+f"(c[1]), "+f"(c[2]), "+f"(c[3])
        : "r"(a[0]), "r"(a[1]), "r"(a[2]), "r"(a[3]), "r"(b[0]), "r"(b[1]));
}

__device__ __forceinline__ void ldsm4(uint32_t* r, uint32_t addr) {
    asm volatile("ldmatrix.sync.aligned.m8n8.x4.shared.b16 {%0,%1,%2,%3}, [%4];"
        : "=r"(r[0]), "=r"(r[1]), "=r"(r[2]), "=r"(r[3]) : "r"(addr));
}

__device__ __forceinline__ void ldsm4t(uint32_t* r, uint32_t addr) {
    asm volatile("ldmatrix.sync.aligned.m8n8.x4.trans.shared.b16 {%0,%1,%2,%3}, [%4];"
        : "=r"(r[0]), "=r"(r[1]), "=r"(r[2]), "=r"(r[3]) : "r"(addr));
}

// ---------------------------------------------------------------------------
// fp16 mma.sync GEMM — proven mainloop (4-stage, wait3, two barriers/chunk,
// cp.async after MMAs). B in NATURAL [K,N] layout, fragments via ldsm.trans
// (same addressing pattern as the validated attention V path).
// C = A[M,K] @ B[K,N] (+bias). 128x128x32 CTA chunk, 256 thr, 8 warps (2x4).
// ---------------------------------------------------------------------------
#define HSTR 40                            // A row stride (halves): 32 + 8 pad
#define BSTR 136                           // B row stride (halves): 128 + 8 pad
#define A_TILE_B (128 * HSTR * 2)          // 10240
#define HSTAGE_BYTES (A_TILE_B + 32 * BSTR * 2)   // 10240 + 8704 = 18944
#define HGEMM_SMEM (4 * HSTAGE_BYTES)      // 75776

template<bool HOUT>
__global__ __launch_bounds__(256) void h16_mma_gemm(
    const __half* __restrict__ A, const __half* __restrict__ B,
    const float* __restrict__ bias, void* __restrict__ Cv,
    int N, int K)
{
    extern __shared__ __align__(128) char smc[];
    const uint32_t sbase = (uint32_t)__cvta_generic_to_shared(smc);

    const int tid = threadIdx.x, lane = tid & 31, w = tid >> 5;
    const int wm = w & 1, wn = w >> 1;           // warp 2x4 grid
    const int g = lane >> 2, tig = lane & 3;
    const int bm = blockIdx.y * 128, bn = blockIdx.x * 128;

    // cp.async A mapping (2 cp16/thread): rows 0-63 and 64-127
    const int r0w = tid >> 2;            // 0..63
    const int c8 = (tid & 3) * 8;        // halves: 0,8,16,24
    const __half* Ag0 = A + (size_t)(bm + r0w) * K + c8;
    const __half* Ag1 = Ag0 + (size_t)64 * K;
    const uint32_t offA0 = (r0w * HSTR + c8) * 2;
    const uint32_t offA1 = ((r0w + 64) * HSTR + c8) * 2;

    // cp.async B mapping (2 cp16/thread): k-rows 0-15 and 16-31, 128 cols
    const int b_r = tid >> 4;            // 0..15
    const int b_c8 = (tid & 15) * 8;     // halves 0..120
    const __half* Bg0 = B + (size_t)b_r * N + bn + b_c8;
    const __half* Bg1 = Bg0 + (size_t)16 * N;
    const size_t bstep = (size_t)32 * N; // per-chunk advance
    const uint32_t offB0 = A_TILE_B + (b_r * BSTR + b_c8) * 2;
    const uint32_t offB1 = A_TILE_B + ((b_r + 16) * BSTR + b_c8) * 2;

    // ldmatrix per-lane offsets
    const uint32_t a_row = (lane & 7) + ((lane >> 3) & 1) * 8;
    const uint32_t a_c8 = (lane >> 4) * 8;
    const uint32_t aAddr0 = sbase + ((wm * 64 + a_row) * HSTR + a_c8) * 2;

    // B (trans): lanes 0-15 -> k-rows, lanes>=16 -> +8 n
    const uint32_t bt_row = lane & 15;
    const uint32_t bt_c8 = (lane >> 4) * 8;
    const uint32_t bAddr0 = sbase + A_TILE_B + (bt_row * BSTR + wn * 32 + bt_c8) * 2;

    const int nchunks = K / 32;

    // Prologue: fill 4 stages
#pragma unroll
    for (int s = 0; s < 4; s++) {
        uint32_t so = sbase + s * HSTAGE_BYTES;
        cp16(so + offA0, Ag0 + s * 32);
        cp16(so + offA1, Ag1 + s * 32);
        cp16(so + offB0, Bg0 + (size_t)s * bstep);
        cp16(so + offB1, Bg1 + (size_t)s * bstep);
        cp_commit();
    }

    float acc[4][4][4] = {};

    for (int c = 0; c < nchunks; c++) {
        cp_wait3();
        __syncthreads();

        const uint32_t st = (c & 3) * HSTAGE_BYTES;

#pragma unroll
        for (int ks = 0; ks < 32; ks += 16) {
            uint32_t afr[4][4];
#pragma unroll
            for (int i = 0; i < 4; i++)
                ldsm4(afr[i], aAddr0 + st + (i * 16 * HSTR + ks) * 2);
            uint32_t bfr[2][4];
#pragma unroll
            for (int jp = 0; jp < 2; jp++)
                ldsm4t(bfr[jp], bAddr0 + st + (ks * BSTR + jp * 16) * 2);
#pragma unroll
            for (int i = 0; i < 4; i++)
#pragma unroll
                for (int jp = 0; jp < 2; jp++) {
                    mma_f16(acc[i][jp * 2],     afr[i], bfr[jp]);
                    mma_f16(acc[i][jp * 2 + 1], afr[i], bfr[jp] + 2);
                }
        }
        __syncthreads();

        if (c + 4 < nchunks) {
            uint32_t so = sbase + (c & 3) * HSTAGE_BYTES;
            const int k0 = (c + 4) * 32;
            cp16(so + offA0, Ag0 + k0);
            cp16(so + offA1, Ag1 + k0);
            cp16(so + offB0, Bg0 + (size_t)(c + 4) * bstep);
            cp16(so + offB1, Bg1 + (size_t)(c + 4) * bstep);
        }
        cp_commit();
    }

#pragma unroll
    for (int i = 0; i < 4; i++) {
        const int r0 = bm + wm * 64 + i * 16 + g;
#pragma unroll
        for (int j = 0; j < 4; j++) {
            const int c0 = bn + wn * 32 + j * 8 + tig * 2;
            float bx = 0.f, by = 0.f;
            if (bias) { bx = bias[c0]; by = bias[c0 + 1]; }
            if (HOUT) {
                __half* C = (__half*)Cv;
                uint32_t o0 = packh2(acc[i][j][0] + bx, acc[i][j][1] + by);
                uint32_t o1 = packh2(acc[i][j][2] + bx, acc[i][j][3] + by);
                *(uint32_t*)&C[(size_t)r0 * N + c0] = o0;
                *(uint32_t*)&C[(size_t)(r0 + 8) * N + c0] = o1;
            } else {
                float* C = (float*)Cv;
                *(float2*)&C[(size_t)r0 * N + c0] =
                    make_float2(acc[i][j][0] + bx, acc[i][j][1] + by);
                *(float2*)&C[(size_t)(r0 + 8) * N + c0] =
                    make_float2(acc[i][j][2] + bx, acc[i][j][3] + by);
            }
        }
    }
}

// ---------------------------------------------------------------------------
// Fused prep: hidden->fp16, w_qkv->fp16, w_out->fp16 (all same layout copy)
// ---------------------------------------------------------------------------
#define F2H_N0 (MROWS * HDIM / 4)          // 1048576 float4 groups
#define F2H_N1 (3 * HDIM * HDIM / 4)       // 786432
#define F2H_N2 (HDIM * HDIM / 4)           // 262144

__global__ __launch_bounds__(256) void f2h_all_kernel(
    const float* __restrict__ hidden, const float* __restrict__ wq,
    const float* __restrict__ wo,
    __half* __restrict__ hh, __half* __restrict__ B1, __half* __restrict__ B2)
{
    int i = blockIdx.x * 256 + threadIdx.x;
    const float* src; __half* dst; int j;
    if (i < F2H_N0)              { src = hidden; dst = hh; j = i; }
    else if (i < F2H_N0 + F2H_N1){ src = wq;     dst = B1; j = i - F2H_N0; }
    else                         { src = wo;     dst = B2; j = i - F2H_N0 - F2H_N1; }
    float4 v = ((const float4*)src)[j];
    ((__half2*)dst)[2 * j]     = __floats2half2_rn(v.x, v.y);
    ((__half2*)dst)[2 * j + 1] = __floats2half2_rn(v.z, v.w);
}

// ---------------------------------------------------------------------------
// RoPE: qkv fp16 -> Q/K/V fp16, coalesced [bh][t][d]. Q pre-scaled 1/8.
// ---------------------------------------------------------------------------
__global__ __launch_bounds__(256) void rope_kernel(
    const __half* __restrict__ qkv,
    __half* __restrict__ Q, __half* __restrict__ K, __half* __restrict__ Vh)
{
    const int bt = blockIdx.x;
    const int b = bt >> 11;
    const int t = bt & 2047;
    const __half* row = qkv + (size_t)bt * (3 * HDIM);
    const float LN1E4_OVER_32 = 0.28782313662425575f;  // ln(10000)/32

#pragma unroll
    for (int it = 0; it < 4; it++) {
        int idx = it * 256 + threadIdx.x;
        int h = idx >> 6;
        int d = idx & 63;
        const __half* base = row + h * (3 * HD);
        float qv = __half2float(base[d]);
        float kv = __half2float(base[HD + d]);
        __half vv = base[2 * HD + d];
        int fi = d & 31;
        float inv = expf(-(float)fi * LN1E4_OVER_32);
        float ang = (float)t * inv;
        float sv, cv;
        sincosf(ang, &sv, &cv);
        float qrot = (d < 32) ? -__half2float(base[d + 32]) : __half2float(base[d - 32]);
        float krot = (d < 32) ? -__half2float(base[HD + d + 32]) : __half2float(base[HD + d - 32]);
        int bh = b * NHEAD + h;
        size_t o = ((size_t)bh * T_SEQ + t) * HD + d;
        Q[o] = __float2half_rn((qv * cv + qrot * sv) * 0.125f);
        K[o] = __float2half_rn(kv * cv + krot * sv);
        Vh[o] = vv;
    }
}

// ---------------------------------------------------------------------------
// Flash attention, all-fp16 MMA, double-buffered K/V, interior-block fast
// path (skip masking when block is strictly causal-interior and fully live).
// ---------------------------------------------------------------------------
#define QHS 72    // half row stride (144B), conflict-free for ldsm/ldsm.trans
#define ATT_SMEM ((128 + 2 * 64 + 2 * 64) * QHS * 2 + 2 * 64 * 4)

__global__ __launch_bounds__(256, 2) void attn_mma_kernel(
    const __half* __restrict__ Q, const __half* __restrict__ K,
    const __half* __restrict__ Vh, const int* __restrict__ amask,
    __half* __restrict__ out)
{
    extern __shared__ __align__(128) char smc[];
    __half* Qs = (__half*)smc;               // [128][QHS]
    __half* Ks = Qs + 128 * QHS;             // [2][64][QHS]
    __half* Vs = Ks + 2 * 64 * QHS;          // [2][64][QHS]
    int* smask = (int*)(Vs + 2 * 64 * QHS);  // [2][64]

    const uint32_t qsb = (uint32_t)__cvta_generic_to_shared(Qs);
    const uint32_t ksb = (uint32_t)__cvta_generic_to_shared(Ks);
    const uint32_t vsb = (uint32_t)__cvta_generic_to_shared(Vs);

    const int tid = threadIdx.x, lane = tid & 31, w = tid >> 5;
    const int g = lane >> 2, tig = lane & 3;
    const int qb = gridDim.x - 1 - blockIdx.x;   // heavy CTAs first
    const int bh = blockIdx.y;
    const int b = bh >> 4, h = bh & 15;

    // Live / fully-live block counts (padding is a prefix mask)
    int livev = (amask[b * T_SEQ + lane * 64] != 0) ? 1 : 0;
    int fullv = (amask[b * T_SEQ + lane * 64 + 63] != 0) ? 1 : 0;
    const int nlive = __popc(__ballot_sync(0xffffffff, livev));
    const int nfull = __popc(__ballot_sync(0xffffffff, fullv));

    // ldmatrix per-lane offsets (halves)
    const uint32_t a_row = (lane & 7) + ((lane >> 3) & 1) * 8;
    const uint32_t a_c8 = (lane >> 4) * 8;
    const uint32_t b_row = (lane & 7) + ((lane >> 4) & 1) * 8;
    const uint32_t b_c8 = ((lane >> 3) & 1) * 8;

    const uint32_t qAddr0 = qsb + ((w * 16 + a_row) * QHS + a_c8) * 2;
    const uint32_t kAddr0 = ksb + (b_row * QHS + b_c8) * 2;

    const uint32_t v_row = lane & 15;
    const uint32_t v_c8 = (lane >> 4) * 8;
    const uint32_t vAddr0 = vsb + (v_row * QHS + v_c8) * 2;

    const uint32_t KSTG = 64 * QHS * 2;   // bytes per K/V stage

    const int tr = tid >> 3, tc8 = (tid & 7) << 3;    // rows 0..31 (+32)

    // Prologue: Q (group) + KV(0) (group)
    const __half* Qg = Q + ((size_t)bh * T_SEQ + qb * 128) * HD;
#pragma unroll
    for (int it = 0; it < 4; it++) {
        int idx = it * 256 + tid;
        int r = idx >> 3, c8 = (idx & 7) << 3;
        cp16(qsb + (r * QHS + c8) * 2, Qg + r * HD + c8);
    }
    cp_commit();

    const __half* Kbase = K + (size_t)bh * T_SEQ * HD;
    const __half* Vbase = Vh + (size_t)bh * T_SEQ * HD;

    {
        cp16(ksb + (tr * QHS + tc8) * 2, Kbase + tr * HD + tc8);
        cp16(ksb + ((tr + 32) * QHS + tc8) * 2, Kbase + (size_t)(tr + 32) * HD + tc8);
        cp16(vsb + (tr * QHS + tc8) * 2, Vbase + tr * HD + tc8);
        cp16(vsb + ((tr + 32) * QHS + tc8) * 2, Vbase + (size_t)(tr + 32) * HD + tc8);
    }
    if (tid < 64) smask[tid] = amask[b * T_SEQ + tid];
    cp_commit();

    float accO[8][4] = {};
    float m0 = -1e30f, m1 = -1e30f, l0 = 0.f, l1 = 0.f;

    const int qrow0 = qb * 128 + w * 16 + g;
    const int qrow1 = qrow0 + 8;
    const int nkb = 2 * qb + 2;
    const int jb_end = (nkb < nlive) ? nkb : nlive;

    for (int jb = 0; jb < jb_end; jb++) {
        const uint32_t s = (jb & 1) * KSTG;
        const uint32_t sn = ((jb + 1) & 1) * KSTG;

        // 1) group(jb) landed
        cp_wait0();
        __syncthreads();

        // 2) issue group(jb+1)
        if (jb + 1 < jb_end) {
            const __half* Kg = Kbase + (size_t)(jb + 1) * 64 * HD;
            const __half* Vg = Vbase + (size_t)(jb + 1) * 64 * HD;
            cp16(ksb + sn + (tr * QHS + tc8) * 2, Kg + tr * HD + tc8);
            cp16(ksb + sn + ((tr + 32) * QHS + tc8) * 2, Kg + (size_t)(tr + 32) * HD + tc8);
            cp16(vsb + sn + (tr * QHS + tc8) * 2, Vg + tr * HD + tc8);
            cp16(vsb + sn + ((tr + 32) * QHS + tc8) * 2, Vg + (size_t)(tr + 32) * HD + tc8);
            if (tid < 64) smask[((jb + 1) & 1) * 64 + tid] = amask[b * T_SEQ + (jb + 1) * 64 + tid];
        }
        cp_commit();

        const int* msk = smask + (jb & 1) * 64;
        const bool fast = (jb < 2 * qb) && (jb < nfull);  // no masking needed

        // 3) S = Q_tile @ K_tile^T (fp16 m16n8k16)
        float sacc[8][4];
#pragma unroll
        for (int j = 0; j < 8; j++)
            sacc[j][0] = sacc[j][1] = sacc[j][2] = sacc[j][3] = 0.f;
#pragma unroll
        for (int ks = 0; ks < 64; ks += 16) {
            uint32_t af[4];
            ldsm4(af, qAddr0 + ks * 2);
#pragma unroll
            for (int jp = 0; jp < 4; jp++) {
                uint32_t bf[4];
                ldsm4(bf, kAddr0 + s + (jp * 16 * QHS + ks) * 2);
                mma_f16(sacc[jp * 2],     af, bf);
                mma_f16(sacc[jp * 2 + 1], af, bf + 2);
            }
        }

        // 4) (mask +) online softmax; P packed to fp16 pairs in registers
        float mx0 = m0, mx1 = m1;
        if (fast) {
#pragma unroll
            for (int j = 0; j < 8; j++) {
                mx0 = fmaxf(mx0, fmaxf(sacc[j][0], sacc[j][1]));
                mx1 = fmaxf(mx1, fmaxf(sacc[j][2], sacc[j][3]));
            }
        } else {
#pragma unroll
            for (int j = 0; j < 8; j++) {
                int c = j * 8 + 2 * tig;
                int colg = jb * 64 + c;
                bool v0 = msk[c]     && (colg     <= qrow0);
                bool v1 = msk[c + 1] && (colg + 1 <= qrow0);
                bool v2 = msk[c]     && (colg     <= qrow1);
                bool v3 = msk[c + 1] && (colg + 1 <= qrow1);
                sacc[j][0] = v0 ? sacc[j][0] : -1e30f;
                sacc[j][1] = v1 ? sacc[j][1] : -1e30f;
                sacc[j][2] = v2 ? sacc[j][2] : -1e30f;
                sacc[j][3] = v3 ? sacc[j][3] : -1e30f;
                mx0 = fmaxf(mx0, fmaxf(sacc[j][0], sacc[j][1]));
                mx1 = fmaxf(mx1, fmaxf(sacc[j][2], sacc[j][3]));
            }
        }
        mx0 = fmaxf(mx0, __shfl_xor_sync(0xffffffff, mx0, 1));
        mx0 = fmaxf(mx0, __shfl_xor_sync(0xffffffff, mx0, 2));
        mx1 = fmaxf(mx1, __shfl_xor_sync(0xffffffff, mx1, 1));
        mx1 = fmaxf(mx1, __shfl_xor_sync(0xffffffff, mx1, 2));
        float corr0 = __expf(m0 - mx0);
        float corr1 = __expf(m1 - mx1);
        m0 = mx0; m1 = mx1;

        uint32_t ph[8][2];
        float sum0 = 0.f, sum1 = 0.f;
#pragma unroll
        for (int j = 0; j < 8; j++) {
            float p0 = __expf(sacc[j][0] - mx0);
            float p1 = __expf(sacc[j][1] - mx0);
            float p2 = __expf(sacc[j][2] - mx1);
            float p3 = __expf(sacc[j][3] - mx1);
            ph[j][0] = packh2(p0, p1);
            ph[j][1] = packh2(p2, p3);
            float2 f0 = __half22float2(*(__half2*)&ph[j][0]);
            float2 f1 = __half22float2(*(__half2*)&ph[j][1]);
            sum0 += f0.x + f0.y;
            sum1 += f1.x + f1.y;
        }
        sum0 += __shfl_xor_sync(0xffffffff, sum0, 1);
        sum0 += __shfl_xor_sync(0xffffffff, sum0, 2);
        sum1 += __shfl_xor_sync(0xffffffff, sum1, 1);
        sum1 += __shfl_xor_sync(0xffffffff, sum1, 2);
        l0 = l0 * corr0 + sum0;
        l1 = l1 * corr1 + sum1;

#pragma unroll
        for (int j = 0; j < 8; j++) {
            accO[j][0] *= corr0; accO[j][1] *= corr0;
            accO[j][2] *= corr1; accO[j][3] *= corr1;
        }

        // 5) PV from Vs[s]
#pragma unroll
        for (int kk = 0; kk < 4; kk++) {
            uint32_t pa[4] = { ph[2 * kk][0], ph[2 * kk][1],
                               ph[2 * kk + 1][0], ph[2 * kk + 1][1] };
#pragma unroll
            for (int jp = 0; jp < 4; jp++) {
                uint32_t bf[4];
                ldsm4t(bf, vAddr0 + s + (kk * 16 * QHS + jp * 16) * 2);
                mma_f16(accO[jp * 2],     pa, bf);
                mma_f16(accO[jp * 2 + 1], pa, bf + 2);
            }
        }
    }

    // ---- epilogue: fp16 output ----
    float inv0 = 1.f / l0, inv1 = 1.f / l1;
    const int r0 = b * T_SEQ + qb * 128 + w * 16 + g;
#pragma unroll
    for (int j = 0; j < 8; j++) {
        int c = h * HD + j * 8 + 2 * tig;
        uint32_t o0 = packh2(accO[j][0] * inv0, accO[j][1] * inv0);
        uint32_t o1 = packh2(accO[j][2] * inv1, accO[j][3] * inv1);
        *(uint32_t*)&out[(size_t)r0 * HDIM + c] = o0;
        *(uint32_t*)&out[(size_t)(r0 + 8) * HDIM + c] = o1;
    }
}

// ---------------------------------------------------------------------------
// Launch
// ---------------------------------------------------------------------------
extern "C" void kernel_launch(void* const* d_in, const int* in_sizes, int n_in,
                              void* d_out, int out_size)
{
    const float* hidden = (const float*)d_in[0];
    const int*   amask  = (const int*)d_in[1];
    const float* w_qkv  = (const float*)d_in[2];
    const float* b_qkv  = (const float*)d_in[3];
    const float* w_out  = (const float*)d_in[4];
    float* out = (float*)d_out;

    __half *qkvh, *hh, *Qh, *Kh, *Vh, *attn, *B1, *B2;
    cudaGetSymbolAddress((void**)&qkvh, g_qkvh);
    cudaGetSymbolAddress((void**)&hh,   g_hh);
    cudaGetSymbolAddress((void**)&Qh,   g_Qh);
    cudaGetSymbolAddress((void**)&Kh,   g_Kh);
    cudaGetSymbolAddress((void**)&Vh,   g_Vh);
    cudaGetSymbolAddress((void**)&attn, g_attn);
    cudaGetSymbolAddress((void**)&B1,   g_B1);
    cudaGetSymbolAddress((void**)&B2,   g_B2);

    cudaFuncSetAttribute(h16_mma_gemm<true>, cudaFuncAttributeMaxDynamicSharedMemorySize,
                         HGEMM_SMEM);
    cudaFuncSetAttribute(h16_mma_gemm<false>, cudaFuncAttributeMaxDynamicSharedMemorySize,
                         HGEMM_SMEM);
    cudaFuncSetAttribute(attn_mma_kernel, cudaFuncAttributeMaxDynamicSharedMemorySize,
                         ATT_SMEM);

    // 0) fused prep: hidden/w_qkv/w_out -> fp16 (natural layouts)
    f2h_all_kernel<<<(F2H_N0 + F2H_N1 + F2H_N2) / 256, 256>>>(
        hidden, w_qkv, w_out, hh, B1, B2);

    // 1) qkv = hidden @ w_qkv + b_qkv -> fp16
    h16_mma_gemm<true><<<dim3(3 * HDIM / 128, MROWS / 128), 256, HGEMM_SMEM>>>(
        hh, B1, b_qkv, qkvh, 3 * HDIM, HDIM);

    // 2) RoPE -> fp16 Q/K/V
    rope_kernel<<<MROWS, 256>>>(qkvh, Qh, Kh, Vh);

    // 3) flash attention -> attn fp16
    attn_mma_kernel<<<dim3(T_SEQ / 128, BATCH * NHEAD), 256, ATT_SMEM>>>(
        Qh, Kh, Vh, amask, attn);

    // 4) out = attn @ w_out -> fp32
    h16_mma_gemm<false><<<dim3(HDIM / 128, MROWS / 128), 256, HGEMM_SMEM>>>(
        attn, B2, nullptr, out, HDIM, HDIM);
}

// round 15
// speedup vs baseline: 1.1766x; 1.0310x over previous
#include <cuda_runtime.h>
#include <cuda_fp16.h>
#include <cstdint>
#include <cstddef>

// Problem constants
#define T_SEQ  2048
#define NHEAD  16
#define HDIM   1024
#define HD     64
#define BATCH  2
#define MROWS  (BATCH * T_SEQ)   // 4096

// Scratch (device globals; no allocations allowed)
__device__ __half g_qkvh[MROWS * 3 * HDIM];           // qkv fp16
__device__ __half g_hh[MROWS * HDIM];                 // hidden fp16
__device__ __half g_Qh[BATCH * NHEAD * T_SEQ * HD];   // [bh][t][d], fp16, scaled by log2e/8
__device__ __half g_Kh[BATCH * NHEAD * T_SEQ * HD];   // [bh][t][d], fp16
__device__ __half g_Vh[BATCH * NHEAD * T_SEQ * HD];   // [bh][t][d], fp16
__device__ __half g_attn[MROWS * HDIM];               // attention output fp16
__device__ __half g_B1[HDIM * 3 * HDIM];              // w_qkv fp16 [K=1024][N=3072]
__device__ __half g_B2[HDIM * HDIM];                  // w_out fp16 [K=1024][N=1024]

// ---------------------------------------------------------------------------
// Helpers
// ---------------------------------------------------------------------------
__device__ __forceinline__ uint32_t packh2(float lo, float hi) {
    uint32_t r;
    asm("cvt.rn.f16x2.f32 %0, %1, %2;" : "=r"(r) : "f"(hi), "f"(lo));
    return r;
}

__device__ __forceinline__ float ex2(float x) {
    float r;
    asm("ex2.approx.f32 %0, %1;" : "=f"(r) : "f"(x));
    return r;
}

__device__ __forceinline__ void cp16(uint32_t dst, const void* src) {
    asm volatile("cp.async.cg.shared.global [%0], [%1], 16;\n" :: "r"(dst), "l"(src));
}
__device__ __forceinline__ void cp_commit() {
    asm volatile("cp.async.commit_group;\n");
}
__device__ __forceinline__ void cp_wait3() {
    asm volatile("cp.async.wait_group 3;\n");
}
__device__ __forceinline__ void cp_wait0() {
    asm volatile("cp.async.wait_group 0;\n");
}

__device__ __forceinline__ void mma_f16(float* c, const uint32_t* a, const uint32_t* b) {
    asm volatile(
        "mma.sync.aligned.m16n8k16.row.col.f32.f16.f16.f32 "
        "{%0,%1,%2,%3}, {%4,%5,%6,%7}, {%8,%9}, {%0,%1,%2,%3};"
        : "+f"(c[0]), "+f"(c[1]), "+f"(c[2]), "+f"(c[3])
        : "r"(a[0]), "r"(a[1]), "r"(a[2]), "r"(a[3]), "r"(b[0]), "r"(b[1]));
}

__device__ __forceinline__ void ldsm4(uint32_t* r, uint32_t addr) {
    asm volatile("ldmatrix.sync.aligned.m8n8.x4.shared.b16 {%0,%1,%2,%3}, [%4];"
        : "=r"(r[0]), "=r"(r[1]), "=r"(r[2]), "=r"(r[3]) : "r"(addr));
}

__device__ __forceinline__ void ldsm4t(uint32_t* r, uint32_t addr) {
    asm volatile("ldmatrix.sync.aligned.m8n8.x4.trans.shared.b16 {%0,%1,%2,%3}, [%4];"
        : "=r"(r[0]), "=r"(r[1]), "=r"(r[2]), "=r"(r[3]) : "r"(addr));
}

// ---------------------------------------------------------------------------
// fp16 mma.sync GEMM — proven mainloop (4-stage, wait3, two barriers/chunk,
// cp.async after MMAs). B in natural [K,N] layout via ldsm.trans.
// ---------------------------------------------------------------------------
#define HSTR 40                            // A row stride (halves): 32 + 8 pad
#define BSTR 136                           // B row stride (halves): 128 + 8 pad
#define A_TILE_B (128 * HSTR * 2)          // 10240
#define HSTAGE_BYTES (A_TILE_B + 32 * BSTR * 2)   // 18944
#define HGEMM_SMEM (4 * HSTAGE_BYTES)      // 75776

template<bool HOUT>
__global__ __launch_bounds__(256) void h16_mma_gemm(
    const __half* __restrict__ A, const __half* __restrict__ B,
    const float* __restrict__ bias, void* __restrict__ Cv,
    int N, int K)
{
    extern __shared__ __align__(128) char smc[];
    const uint32_t sbase = (uint32_t)__cvta_generic_to_shared(smc);

    const int tid = threadIdx.x, lane = tid & 31, w = tid >> 5;
    const int wm = w & 1, wn = w >> 1;
    const int g = lane >> 2, tig = lane & 3;
    const int bm = blockIdx.y * 128, bn = blockIdx.x * 128;

    const int r0w = tid >> 2;
    const int c8 = (tid & 3) * 8;
    const __half* Ag0 = A + (size_t)(bm + r0w) * K + c8;
    const __half* Ag1 = Ag0 + (size_t)64 * K;
    const uint32_t offA0 = (r0w * HSTR + c8) * 2;
    const uint32_t offA1 = ((r0w + 64) * HSTR + c8) * 2;

    const int b_r = tid >> 4;
    const int b_c8 = (tid & 15) * 8;
    const __half* Bg0 = B + (size_t)b_r * N + bn + b_c8;
    const __half* Bg1 = Bg0 + (size_t)16 * N;
    const size_t bstep = (size_t)32 * N;
    const uint32_t offB0 = A_TILE_B + (b_r * BSTR + b_c8) * 2;
    const uint32_t offB1 = A_TILE_B + ((b_r + 16) * BSTR + b_c8) * 2;

    const uint32_t a_row = (lane & 7) + ((lane >> 3) & 1) * 8;
    const uint32_t a_c8 = (lane >> 4) * 8;
    const uint32_t aAddr0 = sbase + ((wm * 64 + a_row) * HSTR + a_c8) * 2;

    const uint32_t bt_row = lane & 15;
    const uint32_t bt_c8 = (lane >> 4) * 8;
    const uint32_t bAddr0 = sbase + A_TILE_B + (bt_row * BSTR + wn * 32 + bt_c8) * 2;

    const int nchunks = K / 32;

#pragma unroll
    for (int s = 0; s < 4; s++) {
        uint32_t so = sbase + s * HSTAGE_BYTES;
        cp16(so + offA0, Ag0 + s * 32);
        cp16(so + offA1, Ag1 + s * 32);
        cp16(so + offB0, Bg0 + (size_t)s * bstep);
        cp16(so + offB1, Bg1 + (size_t)s * bstep);
        cp_commit();
    }

    float acc[4][4][4] = {};

    for (int c = 0; c < nchunks; c++) {
        cp_wait3();
        __syncthreads();

        const uint32_t st = (c & 3) * HSTAGE_BYTES;

#pragma unroll
        for (int ks = 0; ks < 32; ks += 16) {
            uint32_t afr[4][4];
#pragma unroll
            for (int i = 0; i < 4; i++)
                ldsm4(afr[i], aAddr0 + st + (i * 16 * HSTR + ks) * 2);
            uint32_t bfr[2][4];
#pragma unroll
            for (int jp = 0; jp < 2; jp++)
                ldsm4t(bfr[jp], bAddr0 + st + (ks * BSTR + jp * 16) * 2);
#pragma unroll
            for (int i = 0; i < 4; i++)
#pragma unroll
                for (int jp = 0; jp < 2; jp++) {
                    mma_f16(acc[i][jp * 2],     afr[i], bfr[jp]);
                    mma_f16(acc[i][jp * 2 + 1], afr[i], bfr[jp] + 2);
                }
        }
        __syncthreads();

        if (c + 4 < nchunks) {
            uint32_t so = sbase + (c & 3) * HSTAGE_BYTES;
            const int k0 = (c + 4) * 32;
            cp16(so + offA0, Ag0 + k0);
            cp16(so + offA1, Ag1 + k0);
            cp16(so + offB0, Bg0 + (size_t)(c + 4) * bstep);
            cp16(so + offB1, Bg1 + (size_t)(c + 4) * bstep);
        }
        cp_commit();
    }

#pragma unroll
    for (int i = 0; i < 4; i++) {
        const int r0 = bm + wm * 64 + i * 16 + g;
#pragma unroll
        for (int j = 0; j < 4; j++) {
            const int c0 = bn + wn * 32 + j * 8 + tig * 2;
            float bx = 0.f, by = 0.f;
            if (bias) { bx = bias[c0]; by = bias[c0 + 1]; }
            if (HOUT) {
                __half* C = (__half*)Cv;
                uint32_t o0 = packh2(acc[i][j][0] + bx, acc[i][j][1] + by);
                uint32_t o1 = packh2(acc[i][j][2] + bx, acc[i][j][3] + by);
                *(uint32_t*)&C[(size_t)r0 * N + c0] = o0;
                *(uint32_t*)&C[(size_t)(r0 + 8) * N + c0] = o1;
            } else {
                float* C = (float*)Cv;
                *(float2*)&C[(size_t)r0 * N + c0] =
                    make_float2(acc[i][j][0] + bx, acc[i][j][1] + by);
                *(float2*)&C[(size_t)(r0 + 8) * N + c0] =
                    make_float2(acc[i][j][2] + bx, acc[i][j][3] + by);
            }
        }
    }
}

// ---------------------------------------------------------------------------
// Fused prep: hidden->fp16, w_qkv->fp16, w_out->fp16
// ---------------------------------------------------------------------------
#define F2H_N0 (MROWS * HDIM / 4)
#define F2H_N1 (3 * HDIM * HDIM / 4)
#define F2H_N2 (HDIM * HDIM / 4)

__global__ __launch_bounds__(256) void f2h_all_kernel(
    const float* __restrict__ hidden, const float* __restrict__ wq,
    const float* __restrict__ wo,
    __half* __restrict__ hh, __half* __restrict__ B1, __half* __restrict__ B2)
{
    int i = blockIdx.x * 256 + threadIdx.x;
    const float* src; __half* dst; int j;
    if (i < F2H_N0)              { src = hidden; dst = hh; j = i; }
    else if (i < F2H_N0 + F2H_N1){ src = wq;     dst = B1; j = i - F2H_N0; }
    else                         { src = wo;     dst = B2; j = i - F2H_N0 - F2H_N1; }
    float4 v = ((const float4*)src)[j];
    ((__half2*)dst)[2 * j]     = __floats2half2_rn(v.x, v.y);
    ((__half2*)dst)[2 * j + 1] = __floats2half2_rn(v.z, v.w);
}

// ---------------------------------------------------------------------------
// RoPE: qkv fp16 -> Q/K/V fp16, coalesced [bh][t][d].
// Q scaled by (1/8)*log2(e) so softmax can use bare exp2.
// ---------------------------------------------------------------------------
__global__ __launch_bounds__(256) void rope_kernel(
    const __half* __restrict__ qkv,
    __half* __restrict__ Q, __half* __restrict__ K, __half* __restrict__ Vh)
{
    const int bt = blockIdx.x;
    const int b = bt >> 11;
    const int t = bt & 2047;
    const __half* row = qkv + (size_t)bt * (3 * HDIM);
    const float LN1E4_OVER_32 = 0.28782313662425575f;  // ln(10000)/32
    const float QSCALE = 0.125f * 1.4426950408889634f; // (1/8)*log2(e)

#pragma unroll
    for (int it = 0; it < 4; it++) {
        int idx = it * 256 + threadIdx.x;
        int h = idx >> 6;
        int d = idx & 63;
        const __half* base = row + h * (3 * HD);
        float qv = __half2float(base[d]);
        float kv = __half2float(base[HD + d]);
        __half vv = base[2 * HD + d];
        int fi = d & 31;
        float inv = expf(-(float)fi * LN1E4_OVER_32);
        float ang = (float)t * inv;
        float sv, cv;
        sincosf(ang, &sv, &cv);
        float qrot = (d < 32) ? -__half2float(base[d + 32]) : __half2float(base[d - 32]);
        float krot = (d < 32) ? -__half2float(base[HD + d + 32]) : __half2float(base[HD + d - 32]);
        int bh = b * NHEAD + h;
        size_t o = ((size_t)bh * T_SEQ + t) * HD + d;
        Q[o] = __float2half_rn((qv * cv + qrot * sv) * QSCALE);
        K[o] = __float2half_rn(kv * cv + krot * sv);
        Vh[o] = vv;
    }
}

// ---------------------------------------------------------------------------
// Flash attention, all-fp16 MMA, double-buffered K/V, interior fast path,
// exp2-based softmax (log2e folded into Q), fp32 p-sum.
// ---------------------------------------------------------------------------
#define QHS 72
#define ATT_SMEM ((128 + 2 * 64 + 2 * 64) * QHS * 2 + 2 * 64 * 4)

__global__ __launch_bounds__(256, 2) void attn_mma_kernel(
    const __half* __restrict__ Q, const __half* __restrict__ K,
    const __half* __restrict__ Vh, const int* __restrict__ amask,
    __half* __restrict__ out)
{
    extern __shared__ __align__(128) char smc[];
    __half* Qs = (__half*)smc;               // [128][QHS]
    __half* Ks = Qs + 128 * QHS;             // [2][64][QHS]
    __half* Vs = Ks + 2 * 64 * QHS;          // [2][64][QHS]
    int* smask = (int*)(Vs + 2 * 64 * QHS);  // [2][64]

    const uint32_t qsb = (uint32_t)__cvta_generic_to_shared(Qs);
    const uint32_t ksb = (uint32_t)__cvta_generic_to_shared(Ks);
    const uint32_t vsb = (uint32_t)__cvta_generic_to_shared(Vs);

    const int tid = threadIdx.x, lane = tid & 31, w = tid >> 5;
    const int g = lane >> 2, tig = lane & 3;
    const int qb = gridDim.x - 1 - blockIdx.x;   // heavy CTAs first
    const int bh = blockIdx.y;
    const int b = bh >> 4, h = bh & 15;

    // Live / fully-live block counts (padding is a prefix mask)
    int livev = (amask[b * T_SEQ + lane * 64] != 0) ? 1 : 0;
    int fullv = (amask[b * T_SEQ + lane * 64 + 63] != 0) ? 1 : 0;
    const int nlive = __popc(__ballot_sync(0xffffffff, livev));
    const int nfull = __popc(__ballot_sync(0xffffffff, fullv));

    const uint32_t a_row = (lane & 7) + ((lane >> 3) & 1) * 8;
    const uint32_t a_c8 = (lane >> 4) * 8;
    const uint32_t b_row = (lane & 7) + ((lane >> 4) & 1) * 8;
    const uint32_t b_c8 = ((lane >> 3) & 1) * 8;

    const uint32_t qAddr0 = qsb + ((w * 16 + a_row) * QHS + a_c8) * 2;
    const uint32_t kAddr0 = ksb + (b_row * QHS + b_c8) * 2;

    const uint32_t v_row = lane & 15;
    const uint32_t v_c8 = (lane >> 4) * 8;
    const uint32_t vAddr0 = vsb + (v_row * QHS + v_c8) * 2;

    const uint32_t KSTG = 64 * QHS * 2;

    const int tr = tid >> 3, tc8 = (tid & 7) << 3;

    // Prologue: Q (group) + KV(0) (group)
    const __half* Qg = Q + ((size_t)bh * T_SEQ + qb * 128) * HD;
#pragma unroll
    for (int it = 0; it < 4; it++) {
        int idx = it * 256 + tid;
        int r = idx >> 3, c8 = (idx & 7) << 3;
        cp16(qsb + (r * QHS + c8) * 2, Qg + r * HD + c8);
    }
    cp_commit();

    const __half* Kbase = K + (size_t)bh * T_SEQ * HD;
    const __half* Vbase = Vh + (size_t)bh * T_SEQ * HD;

    {
        cp16(ksb + (tr * QHS + tc8) * 2, Kbase + tr * HD + tc8);
        cp16(ksb + ((tr + 32) * QHS + tc8) * 2, Kbase + (size_t)(tr + 32) * HD + tc8);
        cp16(vsb + (tr * QHS + tc8) * 2, Vbase + tr * HD + tc8);
        cp16(vsb + ((tr + 32) * QHS + tc8) * 2, Vbase + (size_t)(tr + 32) * HD + tc8);
    }
    if (tid < 64) smask[tid] = amask[b * T_SEQ + tid];
    cp_commit();

    float accO[8][4] = {};
    float m0 = -1e30f, m1 = -1e30f, l0 = 0.f, l1 = 0.f;

    const int qrow0 = qb * 128 + w * 16 + g;
    const int qrow1 = qrow0 + 8;
    const int nkb = 2 * qb + 2;
    const int jb_end = (nkb < nlive) ? nkb : nlive;

    for (int jb = 0; jb < jb_end; jb++) {
        const uint32_t s = (jb & 1) * KSTG;
        const uint32_t sn = ((jb + 1) & 1) * KSTG;

        cp_wait0();
        __syncthreads();

        if (jb + 1 < jb_end) {
            const __half* Kg = Kbase + (size_t)(jb + 1) * 64 * HD;
            const __half* Vg = Vbase + (size_t)(jb + 1) * 64 * HD;
            cp16(ksb + sn + (tr * QHS + tc8) * 2, Kg + tr * HD + tc8);
            cp16(ksb + sn + ((tr + 32) * QHS + tc8) * 2, Kg + (size_t)(tr + 32) * HD + tc8);
            cp16(vsb + sn + (tr * QHS + tc8) * 2, Vg + tr * HD + tc8);
            cp16(vsb + sn + ((tr + 32) * QHS + tc8) * 2, Vg + (size_t)(tr + 32) * HD + tc8);
            if (tid < 64) smask[((jb + 1) & 1) * 64 + tid] = amask[b * T_SEQ + (jb + 1) * 64 + tid];
        }
        cp_commit();

        const int* msk = smask + (jb & 1) * 64;
        const bool fast = (jb < 2 * qb) && (jb < nfull);

        // S = Q_tile @ K_tile^T (fp16 m16n8k16); S is already in log2 units
        float sacc[8][4];
#pragma unroll
        for (int j = 0; j < 8; j++)
            sacc[j][0] = sacc[j][1] = sacc[j][2] = sacc[j][3] = 0.f;
#pragma unroll
        for (int ks = 0; ks < 64; ks += 16) {
            uint32_t af[4];
            ldsm4(af, qAddr0 + ks * 2);
#pragma unroll
            for (int jp = 0; jp < 4; jp++) {
                uint32_t bf[4];
                ldsm4(bf, kAddr0 + s + (jp * 16 * QHS + ks) * 2);
                mma_f16(sacc[jp * 2],     af, bf);
                mma_f16(sacc[jp * 2 + 1], af, bf + 2);
            }
        }

        // mask + online softmax (exp2)
        float mx0 = m0, mx1 = m1;
        if (fast) {
#pragma unroll
            for (int j = 0; j < 8; j++) {
                mx0 = fmaxf(mx0, fmaxf(sacc[j][0], sacc[j][1]));
                mx1 = fmaxf(mx1, fmaxf(sacc[j][2], sacc[j][3]));
            }
        } else {
#pragma unroll
            for (int j = 0; j < 8; j++) {
                int c = j * 8 + 2 * tig;
                int colg = jb * 64 + c;
                bool v0 = msk[c]     && (colg     <= qrow0);
                bool v1 = msk[c + 1] && (colg + 1 <= qrow0);
                bool v2 = msk[c]     && (colg     <= qrow1);
                bool v3 = msk[c + 1] && (colg + 1 <= qrow1);
                sacc[j][0] = v0 ? sacc[j][0] : -1e30f;
                sacc[j][1] = v1 ? sacc[j][1] : -1e30f;
                sacc[j][2] = v2 ? sacc[j][2] : -1e30f;
                sacc[j][3] = v3 ? sacc[j][3] : -1e30f;
                mx0 = fmaxf(mx0, fmaxf(sacc[j][0], sacc[j][1]));
                mx1 = fmaxf(mx1, fmaxf(sacc[j][2], sacc[j][3]));
            }
        }
        mx0 = fmaxf(mx0, __shfl_xor_sync(0xffffffff, mx0, 1));
        mx0 = fmaxf(mx0, __shfl_xor_sync(0xffffffff, mx0, 2));
        mx1 = fmaxf(mx1, __shfl_xor_sync(0xffffffff, mx1, 1));
        mx1 = fmaxf(mx1, __shfl_xor_sync(0xffffffff, mx1, 2));
        float corr0 = ex2(m0 - mx0);
        float corr1 = ex2(m1 - mx1);
        m0 = mx0; m1 = mx1;

        uint32_t ph[8][2];
        float sum0 = 0.f, sum1 = 0.f;
#pragma unroll
        for (int j = 0; j < 8; j++) {
            float p0 = ex2(sacc[j][0] - mx0);
            float p1 = ex2(sacc[j][1] - mx0);
            float p2 = ex2(sacc[j][2] - mx1);
            float p3 = ex2(sacc[j][3] - mx1);
            ph[j][0] = packh2(p0, p1);
            ph[j][1] = packh2(p2, p3);
            sum0 += p0 + p1;
            sum1 += p2 + p3;
        }
        sum0 += __shfl_xor_sync(0xffffffff, sum0, 1);
        sum0 += __shfl_xor_sync(0xffffffff, sum0, 2);
        sum1 += __shfl_xor_sync(0xffffffff, sum1, 1);
        sum1 += __shfl_xor_sync(0xffffffff, sum1, 2);
        l0 = l0 * corr0 + sum0;
        l1 = l1 * corr1 + sum1;

#pragma unroll
        for (int j = 0; j < 8; j++) {
            accO[j][0] *= corr0; accO[j][1] *= corr0;
            accO[j][2] *= corr1; accO[j][3] *= corr1;
        }

        // PV
#pragma unroll
        for (int kk = 0; kk < 4; kk++) {
            uint32_t pa[4] = { ph[2 * kk][0], ph[2 * kk][1],
                               ph[2 * kk + 1][0], ph[2 * kk + 1][1] };
#pragma unroll
            for (int jp = 0; jp < 4; jp++) {
                uint32_t bf[4];
                ldsm4t(bf, vAddr0 + s + (kk * 16 * QHS + jp * 16) * 2);
                mma_f16(accO[jp * 2],     pa, bf);
                mma_f16(accO[jp * 2 + 1], pa, bf + 2);
            }
        }
    }

    // ---- epilogue: fp16 output ----
    float inv0 = 1.f / l0, inv1 = 1.f / l1;
    const int r0 = b * T_SEQ + qb * 128 + w * 16 + g;
#pragma unroll
    for (int j = 0; j < 8; j++) {
        int c = h * HD + j * 8 + 2 * tig;
        uint32_t o0 = packh2(accO[j][0] * inv0, accO[j][1] * inv0);
        uint32_t o1 = packh2(accO[j][2] * inv1, accO[j][3] * inv1);
        *(uint32_t*)&out[(size_t)r0 * HDIM + c] = o0;
        *(uint32_t*)&out[(size_t)(r0 + 8) * HDIM + c] = o1;
    }
}

// ---------------------------------------------------------------------------
// Launch
// ---------------------------------------------------------------------------
extern "C" void kernel_launch(void* const* d_in, const int* in_sizes, int n_in,
                              void* d_out, int out_size)
{
    const float* hidden = (const float*)d_in[0];
    const int*   amask  = (const int*)d_in[1];
    const float* w_qkv  = (const float*)d_in[2];
    const float* b_qkv  = (const float*)d_in[3];
    const float* w_out  = (const float*)d_in[4];
    float* out = (float*)d_out;

    __half *qkvh, *hh, *Qh, *Kh, *Vh, *attn, *B1, *B2;
    cudaGetSymbolAddress((void**)&qkvh, g_qkvh);
    cudaGetSymbolAddress((void**)&hh,   g_hh);
    cudaGetSymbolAddress((void**)&Qh,   g_Qh);
    cudaGetSymbolAddress((void**)&Kh,   g_Kh);
    cudaGetSymbolAddress((void**)&Vh,   g_Vh);
    cudaGetSymbolAddress((void**)&attn, g_attn);
    cudaGetSymbolAddress((void**)&B1,   g_B1);
    cudaGetSymbolAddress((void**)&B2,   g_B2);

    cudaFuncSetAttribute(h16_mma_gemm<true>, cudaFuncAttributeMaxDynamicSharedMemorySize,
                         HGEMM_SMEM);
    cudaFuncSetAttribute(h16_mma_gemm<false>, cudaFuncAttributeMaxDynamicSharedMemorySize,
                         HGEMM_SMEM);
    cudaFuncSetAttribute(attn_mma_kernel, cudaFuncAttributeMaxDynamicSharedMemorySize,
                         ATT_SMEM);

    // 0) fused prep
    f2h_all_kernel<<<(F2H_N0 + F2H_N1 + F2H_N2) / 256, 256>>>(
        hidden, w_qkv, w_out, hh, B1, B2);

    // 1) qkv = hidden @ w_qkv + b_qkv -> fp16
    h16_mma_gemm<true><<<dim3(3 * HDIM / 128, MROWS / 128), 256, HGEMM_SMEM>>>(
        hh, B1, b_qkv, qkvh, 3 * HDIM, HDIM);

    // 2) RoPE -> fp16 Q/K/V (Q scaled by log2e/8)
    rope_kernel<<<MROWS, 256>>>(qkvh, Qh, Kh, Vh);

    // 3) flash attention -> attn fp16
    attn_mma_kernel<<<dim3(T_SEQ / 128, BATCH * NHEAD), 256, ATT_SMEM>>>(
        Qh, Kh, Vh, amask, attn);

    // 4) out = attn @ w_out -> fp32
    h16_mma_gemm<false><<<dim3(HDIM / 128, MROWS / 128), 256, HGEMM_SMEM>>>(
        attn, B2, nullptr, out, HDIM, HDIM);
}

// round 16
// speedup vs baseline: 1.2190x; 1.0361x over previous
#include <cuda_runtime.h>
#include <cuda_fp16.h>
#include <cstdint>
#include <cstddef>

// Problem constants
#define T_SEQ  2048
#define NHEAD  16
#define HDIM   1024
#define HD     64
#define BATCH  2
#define MROWS  (BATCH * T_SEQ)   // 4096

// Scratch (device globals; no allocations allowed)
__device__ __half g_qkvh[MROWS * 3 * HDIM];           // qkv fp16
__device__ __half g_hh[MROWS * HDIM];                 // hidden fp16
__device__ __half g_Qh[BATCH * NHEAD * T_SEQ * HD];   // [bh][t][d], fp16, scaled log2e/8
__device__ __half g_Kh[BATCH * NHEAD * T_SEQ * HD];   // [bh][t][d], fp16
__device__ __half g_Vh[BATCH * NHEAD * T_SEQ * HD];   // [bh][t][d], fp16
__device__ __half g_attn[MROWS * HDIM];               // attention output fp16
__device__ __half g_B1[HDIM * 3 * HDIM];              // w_qkv fp16 [K=1024][N=3072]
__device__ __half g_B2[HDIM * HDIM];                  // w_out fp16 [K=1024][N=1024]

// ---------------------------------------------------------------------------
// Helpers
// ---------------------------------------------------------------------------
__device__ __forceinline__ uint32_t packh2(float lo, float hi) {
    uint32_t r;
    asm("cvt.rn.f16x2.f32 %0, %1, %2;" : "=r"(r) : "f"(hi), "f"(lo));
    return r;
}

__device__ __forceinline__ float ex2(float x) {
    float r;
    asm("ex2.approx.f32 %0, %1;" : "=f"(r) : "f"(x));
    return r;
}

__device__ __forceinline__ uint32_t ex2h2(uint32_t x) {
    uint32_t r;
    asm("ex2.approx.f16x2 %0, %1;" : "=r"(r) : "r"(x));
    return r;
}

__device__ __forceinline__ void cp16(uint32_t dst, const void* src) {
    asm volatile("cp.async.cg.shared.global [%0], [%1], 16;\n" :: "r"(dst), "l"(src));
}
__device__ __forceinline__ void cp_commit() {
    asm volatile("cp.async.commit_group;\n");
}
__device__ __forceinline__ void cp_wait3() {
    asm volatile("cp.async.wait_group 3;\n");
}
__device__ __forceinline__ void cp_wait0() {
    asm volatile("cp.async.wait_group 0;\n");
}

__device__ __forceinline__ void mma_f16(float* c, const uint32_t* a, const uint32_t* b) {
    asm volatile(
        "mma.sync.aligned.m16n8k16.row.col.f32.f16.f16.f32 "
        "{%0,%1,%2,%3}, {%4,%5,%6,%7}, {%8,%9}, {%0,%1,%2,%3};"
        : "+f"(c[0]), "+f"(c[1]), "+f"(c[2]), "+f"(c[3])
        : "r"(a[0]), "r"(a[1]), "r"(a[2]), "r"(a[3]), "r"(b[0]), "r"(b[1]));
}

__device__ __forceinline__ void ldsm4(uint32_t* r, uint32_t addr) {
    asm volatile("ldmatrix.sync.aligned.m8n8.x4.shared.b16 {%0,%1,%2,%3}, [%4];"
        : "=r"(r[0]), "=r"(r[1]), "=r"(r[2]), "=r"(r[3]) : "r"(addr));
}

__device__ __forceinline__ void ldsm4t(uint32_t* r, uint32_t addr) {
    asm volatile("ldmatrix.sync.aligned.m8n8.x4.trans.shared.b16 {%0,%1,%2,%3}, [%4];"
        : "=r"(r[0]), "=r"(r[1]), "=r"(r[2]), "=r"(r[3]) : "r"(addr));
}

// ---------------------------------------------------------------------------
// fp16 mma.sync GEMM — proven mainloop (4-stage, wait3, two barriers/chunk,
// cp.async after MMAs). B in natural [K,N] layout via ldsm.trans.
// ---------------------------------------------------------------------------
#define HSTR 40                            // A row stride (halves): 32 + 8 pad
#define BSTR 136                           // B row stride (halves): 128 + 8 pad
#define A_TILE_B (128 * HSTR * 2)          // 10240
#define HSTAGE_BYTES (A_TILE_B + 32 * BSTR * 2)   // 18944
#define HGEMM_SMEM (4 * HSTAGE_BYTES)      // 75776

template<bool HOUT>
__global__ __launch_bounds__(256) void h16_mma_gemm(
    const __half* __restrict__ A, const __half* __restrict__ B,
    const float* __restrict__ bias, void* __restrict__ Cv,
    int N, int K)
{
    extern __shared__ __align__(128) char smc[];
    const uint32_t sbase = (uint32_t)__cvta_generic_to_shared(smc);

    const int tid = threadIdx.x, lane = tid & 31, w = tid >> 5;
    const int wm = w & 1, wn = w >> 1;
    const int g = lane >> 2, tig = lane & 3;
    const int bm = blockIdx.y * 128, bn = blockIdx.x * 128;

    const int r0w = tid >> 2;
    const int c8 = (tid & 3) * 8;
    const __half* Ag0 = A + (size_t)(bm + r0w) * K + c8;
    const __half* Ag1 = Ag0 + (size_t)64 * K;
    const uint32_t offA0 = (r0w * HSTR + c8) * 2;
    const uint32_t offA1 = ((r0w + 64) * HSTR + c8) * 2;

    const int b_r = tid >> 4;
    const int b_c8 = (tid & 15) * 8;
    const __half* Bg0 = B + (size_t)b_r * N + bn + b_c8;
    const __half* Bg1 = Bg0 + (size_t)16 * N;
    const size_t bstep = (size_t)32 * N;
    const uint32_t offB0 = A_TILE_B + (b_r * BSTR + b_c8) * 2;
    const uint32_t offB1 = A_TILE_B + ((b_r + 16) * BSTR + b_c8) * 2;

    const uint32_t a_row = (lane & 7) + ((lane >> 3) & 1) * 8;
    const uint32_t a_c8 = (lane >> 4) * 8;
    const uint32_t aAddr0 = sbase + ((wm * 64 + a_row) * HSTR + a_c8) * 2;

    const uint32_t bt_row = lane & 15;
    const uint32_t bt_c8 = (lane >> 4) * 8;
    const uint32_t bAddr0 = sbase + A_TILE_B + (bt_row * BSTR + wn * 32 + bt_c8) * 2;

    const int nchunks = K / 32;

#pragma unroll
    for (int s = 0; s < 4; s++) {
        uint32_t so = sbase + s * HSTAGE_BYTES;
        cp16(so + offA0, Ag0 + s * 32);
        cp16(so + offA1, Ag1 + s * 32);
        cp16(so + offB0, Bg0 + (size_t)s * bstep);
        cp16(so + offB1, Bg1 + (size_t)s * bstep);
        cp_commit();
    }

    float acc[4][4][4] = {};

    for (int c = 0; c < nchunks; c++) {
        cp_wait3();
        __syncthreads();

        const uint32_t st = (c & 3) * HSTAGE_BYTES;

#pragma unroll
        for (int ks = 0; ks < 32; ks += 16) {
            uint32_t afr[4][4];
#pragma unroll
            for (int i = 0; i < 4; i++)
                ldsm4(afr[i], aAddr0 + st + (i * 16 * HSTR + ks) * 2);
            uint32_t bfr[2][4];
#pragma unroll
            for (int jp = 0; jp < 2; jp++)
                ldsm4t(bfr[jp], bAddr0 + st + (ks * BSTR + jp * 16) * 2);
#pragma unroll
            for (int i = 0; i < 4; i++)
#pragma unroll
                for (int jp = 0; jp < 2; jp++) {
                    mma_f16(acc[i][jp * 2],     afr[i], bfr[jp]);
                    mma_f16(acc[i][jp * 2 + 1], afr[i], bfr[jp] + 2);
                }
        }
        __syncthreads();

        if (c + 4 < nchunks) {
            uint32_t so = sbase + (c & 3) * HSTAGE_BYTES;
            const int k0 = (c + 4) * 32;
            cp16(so + offA0, Ag0 + k0);
            cp16(so + offA1, Ag1 + k0);
            cp16(so + offB0, Bg0 + (size_t)(c + 4) * bstep);
            cp16(so + offB1, Bg1 + (size_t)(c + 4) * bstep);
        }
        cp_commit();
    }

#pragma unroll
    for (int i = 0; i < 4; i++) {
        const int r0 = bm + wm * 64 + i * 16 + g;
#pragma unroll
        for (int j = 0; j < 4; j++) {
            const int c0 = bn + wn * 32 + j * 8 + tig * 2;
            float bx = 0.f, by = 0.f;
            if (bias) { bx = bias[c0]; by = bias[c0 + 1]; }
            if (HOUT) {
                __half* C = (__half*)Cv;
                uint32_t o0 = packh2(acc[i][j][0] + bx, acc[i][j][1] + by);
                uint32_t o1 = packh2(acc[i][j][2] + bx, acc[i][j][3] + by);
                *(uint32_t*)&C[(size_t)r0 * N + c0] = o0;
                *(uint32_t*)&C[(size_t)(r0 + 8) * N + c0] = o1;
            } else {
                float* C = (float*)Cv;
                *(float2*)&C[(size_t)r0 * N + c0] =
                    make_float2(acc[i][j][0] + bx, acc[i][j][1] + by);
                *(float2*)&C[(size_t)(r0 + 8) * N + c0] =
                    make_float2(acc[i][j][2] + bx, acc[i][j][3] + by);
            }
        }
    }
}

// ---------------------------------------------------------------------------
// Fused prep: hidden->fp16, w_qkv->fp16, w_out->fp16
// ---------------------------------------------------------------------------
#define F2H_N0 (MROWS * HDIM / 4)
#define F2H_N1 (3 * HDIM * HDIM / 4)
#define F2H_N2 (HDIM * HDIM / 4)

__global__ __launch_bounds__(256) void f2h_all_kernel(
    const float* __restrict__ hidden, const float* __restrict__ wq,
    const float* __restrict__ wo,
    __half* __restrict__ hh, __half* __restrict__ B1, __half* __restrict__ B2)
{
    int i = blockIdx.x * 256 + threadIdx.x;
    const float* src; __half* dst; int j;
    if (i < F2H_N0)              { src = hidden; dst = hh; j = i; }
    else if (i < F2H_N0 + F2H_N1){ src = wq;     dst = B1; j = i - F2H_N0; }
    else                         { src = wo;     dst = B2; j = i - F2H_N0 - F2H_N1; }
    float4 v = ((const float4*)src)[j];
    ((__half2*)dst)[2 * j]     = __floats2half2_rn(v.x, v.y);
    ((__half2*)dst)[2 * j + 1] = __floats2half2_rn(v.z, v.w);
}

// ---------------------------------------------------------------------------
// RoPE: qkv fp16 -> Q/K/V fp16, coalesced. Q scaled by (1/8)*log2(e).
// ---------------------------------------------------------------------------
__global__ __launch_bounds__(256) void rope_kernel(
    const __half* __restrict__ qkv,
    __half* __restrict__ Q, __half* __restrict__ K, __half* __restrict__ Vh)
{
    const int bt = blockIdx.x;
    const int b = bt >> 11;
    const int t = bt & 2047;
    const __half* row = qkv + (size_t)bt * (3 * HDIM);
    const float LN1E4_OVER_32 = 0.28782313662425575f;
    const float QSCALE = 0.125f * 1.4426950408889634f;

#pragma unroll
    for (int it = 0; it < 4; it++) {
        int idx = it * 256 + threadIdx.x;
        int h = idx >> 6;
        int d = idx & 63;
        const __half* base = row + h * (3 * HD);
        float qv = __half2float(base[d]);
        float kv = __half2float(base[HD + d]);
        __half vv = base[2 * HD + d];
        int fi = d & 31;
        float inv = expf(-(float)fi * LN1E4_OVER_32);
        float ang = (float)t * inv;
        float sv, cv;
        sincosf(ang, &sv, &cv);
        float qrot = (d < 32) ? -__half2float(base[d + 32]) : __half2float(base[d - 32]);
        float krot = (d < 32) ? -__half2float(base[HD + d + 32]) : __half2float(base[HD + d - 32]);
        int bh = b * NHEAD + h;
        size_t o = ((size_t)bh * T_SEQ + t) * HD + d;
        Q[o] = __float2half_rn((qv * cv + qrot * sv) * QSCALE);
        K[o] = __float2half_rn(kv * cv + krot * sv);
        Vh[o] = vv;
    }
}

// ---------------------------------------------------------------------------
// Flash attention: all-fp16 MMA, double-buffered K/V, interior fast path,
// exp2 softmax with f16x2 EX2, and l computed via ones-matrix MMA (accL).
// ---------------------------------------------------------------------------
#define QHS 72
#define ATT_SMEM ((128 + 2 * 64 + 2 * 64) * QHS * 2 + 2 * 64 * 4)
#define ONESH2 0x3C003C00u   // {1.0h, 1.0h}

__global__ __launch_bounds__(256, 2) void attn_mma_kernel(
    const __half* __restrict__ Q, const __half* __restrict__ K,
    const __half* __restrict__ Vh, const int* __restrict__ amask,
    __half* __restrict__ out)
{
    extern __shared__ __align__(128) char smc[];
    __half* Qs = (__half*)smc;               // [128][QHS]
    __half* Ks = Qs + 128 * QHS;             // [2][64][QHS]
    __half* Vs = Ks + 2 * 64 * QHS;          // [2][64][QHS]
    int* smask = (int*)(Vs + 2 * 64 * QHS);  // [2][64]

    const uint32_t qsb = (uint32_t)__cvta_generic_to_shared(Qs);
    const uint32_t ksb = (uint32_t)__cvta_generic_to_shared(Ks);
    const uint32_t vsb = (uint32_t)__cvta_generic_to_shared(Vs);

    const int tid = threadIdx.x, lane = tid & 31, w = tid >> 5;
    const int g = lane >> 2, tig = lane & 3;
    const int qb = gridDim.x - 1 - blockIdx.x;   // heavy CTAs first
    const int bh = blockIdx.y;
    const int b = bh >> 4, h = bh & 15;

    int livev = (amask[b * T_SEQ + lane * 64] != 0) ? 1 : 0;
    int fullv = (amask[b * T_SEQ + lane * 64 + 63] != 0) ? 1 : 0;
    const int nlive = __popc(__ballot_sync(0xffffffff, livev));
    const int nfull = __popc(__ballot_sync(0xffffffff, fullv));

    const uint32_t a_row = (lane & 7) + ((lane >> 3) & 1) * 8;
    const uint32_t a_c8 = (lane >> 4) * 8;
    const uint32_t b_row = (lane & 7) + ((lane >> 4) & 1) * 8;
    const uint32_t b_c8 = ((lane >> 3) & 1) * 8;

    const uint32_t qAddr0 = qsb + ((w * 16 + a_row) * QHS + a_c8) * 2;
    const uint32_t kAddr0 = ksb + (b_row * QHS + b_c8) * 2;

    const uint32_t v_row = lane & 15;
    const uint32_t v_c8 = (lane >> 4) * 8;
    const uint32_t vAddr0 = vsb + (v_row * QHS + v_c8) * 2;

    const uint32_t KSTG = 64 * QHS * 2;

    const int tr = tid >> 3, tc8 = (tid & 7) << 3;

    // Prologue
    const __half* Qg = Q + ((size_t)bh * T_SEQ + qb * 128) * HD;
#pragma unroll
    for (int it = 0; it < 4; it++) {
        int idx = it * 256 + tid;
        int r = idx >> 3, c8 = (idx & 7) << 3;
        cp16(qsb + (r * QHS + c8) * 2, Qg + r * HD + c8);
    }
    cp_commit();

    const __half* Kbase = K + (size_t)bh * T_SEQ * HD;
    const __half* Vbase = Vh + (size_t)bh * T_SEQ * HD;

    {
        cp16(ksb + (tr * QHS + tc8) * 2, Kbase + tr * HD + tc8);
        cp16(ksb + ((tr + 32) * QHS + tc8) * 2, Kbase + (size_t)(tr + 32) * HD + tc8);
        cp16(vsb + (tr * QHS + tc8) * 2, Vbase + tr * HD + tc8);
        cp16(vsb + ((tr + 32) * QHS + tc8) * 2, Vbase + (size_t)(tr + 32) * HD + tc8);
    }
    if (tid < 64) smask[tid] = amask[b * T_SEQ + tid];
    cp_commit();

    float accO[8][4] = {};
    float accL[4] = {};                 // row-sums via ones-MMA
    float m0 = -1e30f, m1 = -1e30f;

    const int qrow0 = qb * 128 + w * 16 + g;
    const int qrow1 = qrow0 + 8;
    const int nkb = 2 * qb + 2;
    const int jb_end = (nkb < nlive) ? nkb : nlive;

    const uint32_t ones_b[2] = { ONESH2, ONESH2 };

    for (int jb = 0; jb < jb_end; jb++) {
        const uint32_t s = (jb & 1) * KSTG;
        const uint32_t sn = ((jb + 1) & 1) * KSTG;

        cp_wait0();
        __syncthreads();

        if (jb + 1 < jb_end) {
            const __half* Kg = Kbase + (size_t)(jb + 1) * 64 * HD;
            const __half* Vg = Vbase + (size_t)(jb + 1) * 64 * HD;
            cp16(ksb + sn + (tr * QHS + tc8) * 2, Kg + tr * HD + tc8);
            cp16(ksb + sn + ((tr + 32) * QHS + tc8) * 2, Kg + (size_t)(tr + 32) * HD + tc8);
            cp16(vsb + sn + (tr * QHS + tc8) * 2, Vg + tr * HD + tc8);
            cp16(vsb + sn + ((tr + 32) * QHS + tc8) * 2, Vg + (size_t)(tr + 32) * HD + tc8);
            if (tid < 64) smask[((jb + 1) & 1) * 64 + tid] = amask[b * T_SEQ + (jb + 1) * 64 + tid];
        }
        cp_commit();

        const int* msk = smask + (jb & 1) * 64;
        const bool fast = (jb < 2 * qb) && (jb < nfull);

        // S = Q_tile @ K_tile^T (log2 units)
        float sacc[8][4];
#pragma unroll
        for (int j = 0; j < 8; j++)
            sacc[j][0] = sacc[j][1] = sacc[j][2] = sacc[j][3] = 0.f;
#pragma unroll
        for (int ks = 0; ks < 64; ks += 16) {
            uint32_t af[4];
            ldsm4(af, qAddr0 + ks * 2);
#pragma unroll
            for (int jp = 0; jp < 4; jp++) {
                uint32_t bf[4];
                ldsm4(bf, kAddr0 + s + (jp * 16 * QHS + ks) * 2);
                mma_f16(sacc[jp * 2],     af, bf);
                mma_f16(sacc[jp * 2 + 1], af, bf + 2);
            }
        }

        // mask + online softmax (exp2, f16x2)
        float mx0 = m0, mx1 = m1;
        if (fast) {
#pragma unroll
            for (int j = 0; j < 8; j++) {
                mx0 = fmaxf(mx0, fmaxf(sacc[j][0], sacc[j][1]));
                mx1 = fmaxf(mx1, fmaxf(sacc[j][2], sacc[j][3]));
            }
        } else {
#pragma unroll
            for (int j = 0; j < 8; j++) {
                int c = j * 8 + 2 * tig;
                int colg = jb * 64 + c;
                bool v0 = msk[c]     && (colg     <= qrow0);
                bool v1 = msk[c + 1] && (colg + 1 <= qrow0);
                bool v2 = msk[c]     && (colg     <= qrow1);
                bool v3 = msk[c + 1] && (colg + 1 <= qrow1);
                sacc[j][0] = v0 ? sacc[j][0] : -1e30f;
                sacc[j][1] = v1 ? sacc[j][1] : -1e30f;
                sacc[j][2] = v2 ? sacc[j][2] : -1e30f;
                sacc[j][3] = v3 ? sacc[j][3] : -1e30f;
                mx0 = fmaxf(mx0, fmaxf(sacc[j][0], sacc[j][1]));
                mx1 = fmaxf(mx1, fmaxf(sacc[j][2], sacc[j][3]));
            }
        }
        mx0 = fmaxf(mx0, __shfl_xor_sync(0xffffffff, mx0, 1));
        mx0 = fmaxf(mx0, __shfl_xor_sync(0xffffffff, mx0, 2));
        mx1 = fmaxf(mx1, __shfl_xor_sync(0xffffffff, mx1, 1));
        mx1 = fmaxf(mx1, __shfl_xor_sync(0xffffffff, mx1, 2));
        float corr0 = ex2(m0 - mx0);
        float corr1 = ex2(m1 - mx1);
        m0 = mx0; m1 = mx1;

        uint32_t ph[8][2];
#pragma unroll
        for (int j = 0; j < 8; j++) {
            float d0 = sacc[j][0] - mx0;
            float d1 = sacc[j][1] - mx0;
            float d2 = sacc[j][2] - mx1;
            float d3 = sacc[j][3] - mx1;
            ph[j][0] = ex2h2(packh2(d0, d1));
            ph[j][1] = ex2h2(packh2(d2, d3));
        }

        // rescale accumulators (accL uses same corr as accO)
#pragma unroll
        for (int j = 0; j < 8; j++) {
            accO[j][0] *= corr0; accO[j][1] *= corr0;
            accO[j][2] *= corr1; accO[j][3] *= corr1;
        }
        accL[0] *= corr0; accL[1] *= corr0;
        accL[2] *= corr1; accL[3] *= corr1;

        // PV + L-sum MMAs
#pragma unroll
        for (int kk = 0; kk < 4; kk++) {
            uint32_t pa[4] = { ph[2 * kk][0], ph[2 * kk][1],
                               ph[2 * kk + 1][0], ph[2 * kk + 1][1] };
            mma_f16(accL, pa, ones_b);
#pragma unroll
            for (int jp = 0; jp < 4; jp++) {
                uint32_t bf[4];
                ldsm4t(bf, vAddr0 + s + (kk * 16 * QHS + jp * 16) * 2);
                mma_f16(accO[jp * 2],     pa, bf);
                mma_f16(accO[jp * 2 + 1], pa, bf + 2);
            }
        }
    }

    // ---- epilogue: fp16 output (l from accL) ----
    float inv0 = 1.f / accL[0], inv1 = 1.f / accL[2];
    const int r0 = b * T_SEQ + qb * 128 + w * 16 + g;
#pragma unroll
    for (int j = 0; j < 8; j++) {
        int c = h * HD + j * 8 + 2 * tig;
        uint32_t o0 = packh2(accO[j][0] * inv0, accO[j][1] * inv0);
        uint32_t o1 = packh2(accO[j][2] * inv1, accO[j][3] * inv1);
        *(uint32_t*)&out[(size_t)r0 * HDIM + c] = o0;
        *(uint32_t*)&out[(size_t)(r0 + 8) * HDIM + c] = o1;
    }
}

// ---------------------------------------------------------------------------
// Launch
// ---------------------------------------------------------------------------
extern "C" void kernel_launch(void* const* d_in, const int* in_sizes, int n_in,
                              void* d_out, int out_size)
{
    const float* hidden = (const float*)d_in[0];
    const int*   amask  = (const int*)d_in[1];
    const float* w_qkv  = (const float*)d_in[2];
    const float* b_qkv  = (const float*)d_in[3];
    const float* w_out  = (const float*)d_in[4];
    float* out = (float*)d_out;

    __half *qkvh, *hh, *Qh, *Kh, *Vh, *attn, *B1, *B2;
    cudaGetSymbolAddress((void**)&qkvh, g_qkvh);
    cudaGetSymbolAddress((void**)&hh,   g_hh);
    cudaGetSymbolAddress((void**)&Qh,   g_Qh);
    cudaGetSymbolAddress((void**)&Kh,   g_Kh);
    cudaGetSymbolAddress((void**)&Vh,   g_Vh);
    cudaGetSymbolAddress((void**)&attn, g_attn);
    cudaGetSymbolAddress((void**)&B1,   g_B1);
    cudaGetSymbolAddress((void**)&B2,   g_B2);

    cudaFuncSetAttribute(h16_mma_gemm<true>, cudaFuncAttributeMaxDynamicSharedMemorySize,
                         HGEMM_SMEM);
    cudaFuncSetAttribute(h16_mma_gemm<false>, cudaFuncAttributeMaxDynamicSharedMemorySize,
                         HGEMM_SMEM);
    cudaFuncSetAttribute(attn_mma_kernel, cudaFuncAttributeMaxDynamicSharedMemorySize,
                         ATT_SMEM);

    // 0) fused prep
    f2h_all_kernel<<<(F2H_N0 + F2H_N1 + F2H_N2) / 256, 256>>>(
        hidden, w_qkv, w_out, hh, B1, B2);

    // 1) qkv = hidden @ w_qkv + b_qkv -> fp16
    h16_mma_gemm<true><<<dim3(3 * HDIM / 128, MROWS / 128), 256, HGEMM_SMEM>>>(
        hh, B1, b_qkv, qkvh, 3 * HDIM, HDIM);

    // 2) RoPE -> fp16 Q/K/V (Q scaled by log2e/8)
    rope_kernel<<<MROWS, 256>>>(qkvh, Qh, Kh, Vh);

    // 3) flash attention -> attn fp16
    attn_mma_kernel<<<dim3(T_SEQ / 128, BATCH * NHEAD), 256, ATT_SMEM>>>(
        Qh, Kh, Vh, amask, attn);

    // 4) out = attn @ w_out -> fp32
    h16_mma_gemm<false><<<dim3(HDIM / 128, MROWS / 128), 256, HGEMM_SMEM>>>(
        attn, B2, nullptr, out, HDIM, HDIM);
}